// round 8
// baseline (speedup 1.0000x reference)
#include <cuda_runtime.h>
#include <cuda_bf16.h>
#include <math.h>
#include <stdint.h>

#define D_IN   1024
#define D_H    2048
#define BATCH  256
#define D_OUT  1000
#define EPSV   1e-12f
#define STEPS  30

// ---- bf16 aux GEMM smem geometry (x_proj / head, 128-thread kernel) ----
#define ROW_B      144
#define TILE_A_HI  0
#define TILE_A_LO  9216
#define TILE_B_HI  18432
#define TILE_B_LO  27648
#define STAGE_BYTES 36864
#define SMEM_BYTES  (2 * STAGE_BYTES)

// ---- step GEMM smem: BK=128, 4 tiles of 64 rows x 256B pad to 272B ----
#define SROW     272
#define STILE    (64 * SROW)          // 17408
#define S_AH     0
#define S_AL     17408
#define S_BH     34816
#define S_BL     52224
#define S_STAGE  69632
#define S_DATA   128                  // mbarriers live below this
#define S_SMEM   (S_DATA + 2 * S_STAGE)   // 139392
#define S_TX     65536                // bytes per stage (4 tiles x 16KB)

// ---------------- device scratch (no allocations allowed) ----------------
__device__ float g_t[D_IN];
__device__ float g_s[D_H];
__device__ float g_scal[4];            // [1] = 1/sigma
__device__ float g_xproj[BATCH * D_H];
__device__ float g_xpb[3][BATCH * D_H];  // xproj + bias_l, per layer
__device__ float g_hA[BATCH * D_H];
__device__ float g_hB[BATCH * D_H];

__device__ __nv_bfloat16 g_W0hi[D_H * D_H], g_W0lo[D_H * D_H];
__device__ __nv_bfloat16 g_W1hi[D_H * D_H], g_W1lo[D_H * D_H];
__device__ __nv_bfloat16 g_W2hi[D_H * D_H], g_W2lo[D_H * D_H];
__device__ __nv_bfloat16 g_Winhi[D_H * D_IN], g_Winlo[D_H * D_IN];
__device__ __nv_bfloat16 g_Hdhi[D_OUT * D_H], g_Hdlo[D_OUT * D_H];
__device__ __nv_bfloat16 g_xhi[BATCH * D_IN], g_xlo[BATCH * D_IN];
__device__ __nv_bfloat16 g_hhiA[BATCH * D_H], g_hloA[BATCH * D_H];
__device__ __nv_bfloat16 g_hhiB[BATCH * D_H], g_hloB[BATCH * D_H];

// ---------------- portable PTX helpers ----------------
__device__ __forceinline__ uint32_t smem_u32(const void* p) {
    uint32_t a;
    asm("{ .reg .u64 t; cvta.to.shared.u64 t, %1; cvt.u32.u64 %0, t; }" : "=r"(a) : "l"(p));
    return a;
}
#define CP16(dst, src) asm volatile("cp.async.cg.shared.global [%0], [%1], 16;" :: "r"(dst), "l"(src))
#define CP_COMMIT()    asm volatile("cp.async.commit_group;" ::: "memory")
#define CP_WAIT(n)     asm volatile("cp.async.wait_group %0;" :: "n"(n) : "memory")

// sm_90 base features (valid on plain sm_103 target):
#define MBAR_INIT(a, c) asm volatile("mbarrier.init.shared.b64 [%0], %1;" :: "r"(a), "r"(c) : "memory")
#define MBAR_EXPECT(a, bytes) \
    asm volatile("mbarrier.arrive.expect_tx.shared.b64 _, [%0], %1;" :: "r"(a), "r"(bytes) : "memory")
#define BULK256(dst, src, mbar) \
    asm volatile("cp.async.bulk.shared::cluster.global.mbarrier::complete_tx::bytes [%0], [%1], 256, [%2];" \
        :: "r"(dst), "l"(src), "r"(mbar) : "memory")
#define MBAR_WAIT(mbar, parity) do {                                              \
    uint32_t _m = (mbar), _p = (parity), _d;                                      \
    asm volatile("{ .reg .pred p; mbarrier.try_wait.parity.acquire.cta.shared::cta.b64 p, [%1], %2; selp.b32 %0, 1, 0, p; }" \
        : "=r"(_d) : "r"(_m), "r"(_p) : "memory");                                \
    if (!_d) {                                                                    \
        asm volatile("{ .reg .pred P1; WL_%=: mbarrier.try_wait.parity.acquire.cta.shared::cta.b64 P1, [%0], %1, 0x989680; @P1 bra.uni WD_%=; bra.uni WL_%=; WD_%=: }" \
            :: "r"(_m), "r"(_p) : "memory");                                      \
    }                                                                             \
} while (0)

__device__ __forceinline__ void ldsm4(uint32_t* r, uint32_t addr) {
    asm volatile("ldmatrix.sync.aligned.m8n8.x4.shared.b16 {%0,%1,%2,%3}, [%4];"
        : "=r"(r[0]), "=r"(r[1]), "=r"(r[2]), "=r"(r[3]) : "r"(addr));
}
__device__ __forceinline__ void mma_bf16(float* c, const uint32_t* a, const uint32_t* b) {
    asm volatile("mma.sync.aligned.m16n8k16.row.col.f32.bf16.bf16.f32 "
        "{%0,%1,%2,%3}, {%4,%5,%6,%7}, {%8,%9}, {%0,%1,%2,%3};"
        : "+f"(c[0]), "+f"(c[1]), "+f"(c[2]), "+f"(c[3])
        : "r"(a[0]), "r"(a[1]), "r"(a[2]), "r"(a[3]), "r"(b[0]), "r"(b[1]));
}

// ---------------- small kernels ----------------
__global__ void zero_kernel(float* p, int n) {
    int i = blockIdx.x * blockDim.x + threadIdx.x;
    if (i < n) p[i] = 0.0f;
}
__global__ void split_kernel(const float* __restrict__ src,
                             __nv_bfloat16* __restrict__ hi,
                             __nv_bfloat16* __restrict__ lo, int n) {
    int i = blockIdx.x * blockDim.x + threadIdx.x;
    if (i >= n) return;
    float a = src[i];
    __nv_bfloat16 h = __float2bfloat16(a);
    hi[i] = h;
    lo[i] = __float2bfloat16(a - __bfloat162float(h));
}
__global__ void add_bias_kernel(const float* __restrict__ xp,
                                const float* __restrict__ b,
                                float* __restrict__ dst, int n) {
    int i = blockIdx.x * blockDim.x + threadIdx.x;
    if (i < n) dst[i] = xp[i] + b[i & (D_H - 1)];
}
__global__ void matvec_t_kernel(const float* __restrict__ W, const float* __restrict__ u,
                                float* __restrict__ t) {
    int j = blockIdx.x * blockDim.x + threadIdx.x;
    if (j >= D_IN) return;
    float acc = 0.0f;
#pragma unroll 4
    for (int i = 0; i < D_H; i++) acc = fmaf(W[(size_t)i * D_IN + j], u[i], acc);
    t[j] = acc;
}
__global__ void reduce_t_kernel(const float* __restrict__ t, float* __restrict__ scal) {
    __shared__ float sh[1024];
    int tid = threadIdx.x;
    float v = t[tid];
    sh[tid] = v * v;
    __syncthreads();
    for (int o = 512; o > 0; o >>= 1) { if (tid < o) sh[tid] += sh[tid + o]; __syncthreads(); }
    if (tid == 0) scal[0] = 1.0f / (sqrtf(sh[0]) + EPSV);
}
__global__ void matvec_s_kernel(const float* __restrict__ W, const float* __restrict__ t,
                                const float* __restrict__ scal, float* __restrict__ s) {
    int gtid = blockIdx.x * blockDim.x + threadIdx.x;
    int warp = gtid >> 5, lane = gtid & 31;
    float invn = scal[0];
    for (int r = warp; r < D_H; r += 512) {
        const float* row = W + (size_t)r * D_IN;
        float acc = 0.0f;
        for (int j = lane; j < D_IN; j += 32) acc = fmaf(row[j], t[j], acc);
#pragma unroll
        for (int o = 16; o > 0; o >>= 1) acc += __shfl_xor_sync(0xffffffffu, acc, o);
        if (lane == 0) s[r] = acc * invn;
    }
}
__global__ void reduce_s_kernel(const float* __restrict__ s, float* __restrict__ scal) {
    __shared__ float sh[1024];
    int tid = threadIdx.x;
    float a = s[tid], b = s[tid + 1024];
    sh[tid] = a * a + b * b;
    __syncthreads();
    for (int o = 512; o > 0; o >>= 1) { if (tid < o) sh[tid] += sh[tid + o]; __syncthreads(); }
    if (tid == 0) { float q = sh[0]; scal[1] = (sqrtf(q) + EPSV) / q; }
}

// ================= bf16 3-pass aux GEMM (x_proj MODE 0, head MODE 2) =================
template <int MODE>
__device__ __forceinline__ void epi_elem(float r, int m, int n,
        const float* __restrict__ bias, float* __restrict__ outF,
        float scale, int NB, int ldOut) {
    if (MODE == 0) {
        outF[(size_t)m * ldOut + n] = fmaf(r, scale, bias[n]);
    } else {
        if (n < NB) outF[(size_t)m * ldOut + n] = r + bias[n];
    }
}

__device__ __forceinline__ void prefetch_chunk(uint32_t sb_u, char* sb_p, int k0,
        const __nv_bfloat16* __restrict__ Ahi, const __nv_bfloat16* __restrict__ Alo,
        const __nv_bfloat16* __restrict__ Bhi, const __nv_bfloat16* __restrict__ Blo,
        int K, int NB, int m0, int n0) {
    const int t = threadIdx.x;
#pragma unroll
    for (int r = 0; r < 4; r++) {
        const int idx = t + (r << 7);
        const int row = idx >> 3;
        const int c   = idx & 7;
        const uint32_t soff = (uint32_t)row * ROW_B + (c << 4);
        const size_t ga = (size_t)(m0 + row) * K + k0 + (c << 3);
        CP16(sb_u + TILE_A_HI + soff, Ahi + ga);
        CP16(sb_u + TILE_A_LO + soff, Alo + ga);
        const int gn = n0 + row;
        if (gn < NB) {
            const size_t gb = (size_t)gn * K + k0 + (c << 3);
            CP16(sb_u + TILE_B_HI + soff, Bhi + gb);
            CP16(sb_u + TILE_B_LO + soff, Blo + gb);
        } else {
            const uint4 z = make_uint4(0, 0, 0, 0);
            *reinterpret_cast<uint4*>(sb_p + TILE_B_HI + soff) = z;
            *reinterpret_cast<uint4*>(sb_p + TILE_B_LO + soff) = z;
        }
    }
}

template <int MODE>
__global__ void __launch_bounds__(128)
gemm_mma(const __nv_bfloat16* __restrict__ Ahi, const __nv_bfloat16* __restrict__ Alo,
         const __nv_bfloat16* __restrict__ Bhi, const __nv_bfloat16* __restrict__ Blo,
         const float* __restrict__ bias, float* __restrict__ outF,
         const float* __restrict__ scale_ptr, int K, int NB, int ldOut) {
    extern __shared__ char smem[];
    const uint32_t sbase = smem_u32(smem);
    const int tid  = threadIdx.x;
    const int lane = tid & 31;
    const int wid  = tid >> 5;
    const int m0 = blockIdx.y * 64;
    const int n0 = blockIdx.x * 64;
    const int wm = (wid >> 1) << 5;
    const int wn = (wid & 1) << 5;
    const int NC = K >> 6;

    const int arow  = (lane & 7) | (((lane >> 3) & 1) << 3);
    const int akoff = ((lane >> 4) & 1) << 3;
    const int brow  = (lane & 7) | (((lane >> 4) & 1) << 3);
    const int bkoff = ((lane >> 3) & 1) << 3;

    float acc[2][4][4] = {};

    prefetch_chunk(sbase, smem, 0, Ahi, Alo, Bhi, Blo, K, NB, m0, n0);
    CP_COMMIT();

    for (int c = 0; c < NC; c++) {
        if (c + 1 < NC) {
            const int ns = (c + 1) & 1;
            prefetch_chunk(sbase + ns * STAGE_BYTES, smem + ns * STAGE_BYTES,
                           (c + 1) << 6, Ahi, Alo, Bhi, Blo, K, NB, m0, n0);
            CP_COMMIT();
            CP_WAIT(1);
        } else {
            CP_WAIT(0);
        }
        __syncthreads();

        const uint32_t st = sbase + (c & 1) * STAGE_BYTES;
#pragma unroll
        for (int kk = 0; kk < 4; kk++) {
            const int k0 = kk << 4;
            uint32_t ah[2][4], al[2][4], bh[2][4], bl[2][4];
#pragma unroll
            for (int a = 0; a < 2; a++) {
                const uint32_t off = (uint32_t)(wm + (a << 4) + arow) * ROW_B +
                                     ((k0 + akoff) << 1);
                ldsm4(ah[a], st + TILE_A_HI + off);
                ldsm4(al[a], st + TILE_A_LO + off);
            }
#pragma unroll
            for (int b = 0; b < 2; b++) {
                const uint32_t off = (uint32_t)(wn + (b << 4) + brow) * ROW_B +
                                     ((k0 + bkoff) << 1);
                ldsm4(bh[b], st + TILE_B_HI + off);
                ldsm4(bl[b], st + TILE_B_LO + off);
            }
#pragma unroll
            for (int a = 0; a < 2; a++)
#pragma unroll
                for (int j = 0; j < 4; j++)
                    mma_bf16(acc[a][j], ah[a], &bh[j >> 1][(j & 1) << 1]);
#pragma unroll
            for (int a = 0; a < 2; a++)
#pragma unroll
                for (int j = 0; j < 4; j++)
                    mma_bf16(acc[a][j], ah[a], &bl[j >> 1][(j & 1) << 1]);
#pragma unroll
            for (int a = 0; a < 2; a++)
#pragma unroll
                for (int j = 0; j < 4; j++)
                    mma_bf16(acc[a][j], al[a], &bh[j >> 1][(j & 1) << 1]);
        }
        __syncthreads();
    }

    const float scale = (MODE == 0) ? *scale_ptr : 1.0f;
    const int g  = lane >> 2;
    const int i2 = (lane & 3) << 1;
#pragma unroll
    for (int a = 0; a < 2; a++)
#pragma unroll
        for (int j = 0; j < 4; j++)
#pragma unroll
            for (int e = 0; e < 4; e++) {
                const int m = m0 + wm + (a << 4) + g + ((e >> 1) << 3);
                const int n = n0 + wn + (j << 3) + i2 + (e & 1);
                epi_elem<MODE>(acc[a][j][e], m, n, bias, outF, scale, NB, ldOut);
            }
}

// ================= step GEMM: bf16 3-pass, 256 threads, BK=128, bulk-copy =========
// Loads via cp.async.bulk (256B row per thread) completing on per-stage mbarrier.
// hn = 0.5*hold + 0.5*tanh(xpb + acc); outF=hn; outHi/Lo = bf16 split(hn)
__device__ __forceinline__ void issue_bulk(uint32_t data_u, uint32_t mbar, int k0,
        const __nv_bfloat16* __restrict__ Ahi, const __nv_bfloat16* __restrict__ Alo,
        const __nv_bfloat16* __restrict__ Bhi, const __nv_bfloat16* __restrict__ Blo,
        int m0, int n0) {
    const int t = threadIdx.x;
    const int tile = t >> 6;        // 0..3
    const int row  = t & 63;
    const __nv_bfloat16* src;
    if (tile == 0)      src = Ahi + (size_t)(m0 + row) * D_H + k0;
    else if (tile == 1) src = Alo + (size_t)(m0 + row) * D_H + k0;
    else if (tile == 2) src = Bhi + (size_t)(n0 + row) * D_H + k0;
    else                src = Blo + (size_t)(n0 + row) * D_H + k0;
    const uint32_t dst = data_u + (uint32_t)tile * STILE + (uint32_t)row * SROW;
    BULK256(dst, src, mbar);
}

__global__ void __launch_bounds__(256)
gemm_step(const __nv_bfloat16* __restrict__ Ahi, const __nv_bfloat16* __restrict__ Alo,
          const __nv_bfloat16* __restrict__ Bhi, const __nv_bfloat16* __restrict__ Blo,
          const float* __restrict__ xpb, const float* __restrict__ hold,
          float* __restrict__ outF,
          __nv_bfloat16* __restrict__ outHi, __nv_bfloat16* __restrict__ outLo) {
    extern __shared__ char smem[];
    const uint32_t sbase = smem_u32(smem);
    const uint32_t data0 = sbase + S_DATA;
    const int tid  = threadIdx.x;
    const int lane = tid & 31;
    const int wid  = tid >> 5;
    const int m0 = blockIdx.y * 64;
    const int n0 = blockIdx.x * 64;
    const int wm = (wid >> 2) << 5;   // 0 or 32
    const int wn = (wid & 3) << 4;    // 0,16,32,48
    const int NC = D_H >> 7;          // 16 chunks of 128

    const int arow  = (lane & 7) | (((lane >> 3) & 1) << 3);
    const int akoff = ((lane >> 4) & 1) << 3;
    const int brow  = (lane & 7) | (((lane >> 4) & 1) << 3);
    const int bkoff = ((lane >> 3) & 1) << 3;

    float accm[2][2][4] = {};   // main: ah*bh
    float accc[2][2][4] = {};   // corrections: ah*bl + al*bh

    // mbarriers at sbase+0 (stage0), sbase+8 (stage1)
    if (tid == 0) { MBAR_INIT(sbase + 0, 1); MBAR_INIT(sbase + 8, 1); }
    __syncthreads();

    // prologue: stage 0, chunk 0
    if (tid == 0) MBAR_EXPECT(sbase + 0, S_TX);
    __syncthreads();
    issue_bulk(data0, sbase + 0, 0, Ahi, Alo, Bhi, Blo, m0, n0);

    int ph0 = 0, ph1 = 0;

    for (int c = 0; c < NC; c++) {
        const int s = c & 1;
        if (c + 1 < NC) {
            const int ns = s ^ 1;
            // all threads have finished reading stage ns (consumed at iter c-1,
            // joined by the __syncthreads below before any bulk writes land)
            if (tid == 0) MBAR_EXPECT(sbase + 8 * ns, S_TX);
            __syncthreads();
            issue_bulk(data0 + ns * S_STAGE, sbase + 8 * ns, (c + 1) << 7,
                       Ahi, Alo, Bhi, Blo, m0, n0);
        }
        // wait for stage s data
        if (s == 0) { MBAR_WAIT(sbase + 0, ph0); ph0 ^= 1; }
        else        { MBAR_WAIT(sbase + 8, ph1); ph1 ^= 1; }

        const uint32_t st = data0 + s * S_STAGE;
#pragma unroll
        for (int kk = 0; kk < 8; kk++) {
            const int k0 = kk << 4;
            uint32_t ah[2][4], al[2][4], bh[4], bl[4];
#pragma unroll
            for (int a = 0; a < 2; a++) {
                const uint32_t off = (uint32_t)(wm + (a << 4) + arow) * SROW +
                                     ((k0 + akoff) << 1);
                ldsm4(ah[a], st + S_AH + off);
                ldsm4(al[a], st + S_AL + off);
            }
            {
                const uint32_t off = (uint32_t)(wn + brow) * SROW + ((k0 + bkoff) << 1);
                ldsm4(bh, st + S_BH + off);
                ldsm4(bl, st + S_BL + off);
            }
#pragma unroll
            for (int a = 0; a < 2; a++)
#pragma unroll
                for (int j = 0; j < 2; j++)
                    mma_bf16(accm[a][j], ah[a], &bh[j << 1]);
#pragma unroll
            for (int a = 0; a < 2; a++)
#pragma unroll
                for (int j = 0; j < 2; j++)
                    mma_bf16(accc[a][j], ah[a], &bl[j << 1]);
#pragma unroll
            for (int a = 0; a < 2; a++)
#pragma unroll
                for (int j = 0; j < 2; j++)
                    mma_bf16(accc[a][j], al[a], &bh[j << 1]);
        }
    }

    // epilogue: vectorized 2-wide (n even pairs)
    const int g  = lane >> 2;
    const int i2 = (lane & 3) << 1;
#pragma unroll
    for (int a = 0; a < 2; a++)
#pragma unroll
        for (int j = 0; j < 2; j++)
#pragma unroll
            for (int eh = 0; eh < 2; eh++) {
                const int m = m0 + wm + (a << 4) + g + (eh << 3);
                const int n = n0 + wn + (j << 3) + i2;
                const size_t idx = (size_t)m * D_H + n;
                const float r0 = accm[a][j][eh * 2 + 0] + accc[a][j][eh * 2 + 0];
                const float r1 = accm[a][j][eh * 2 + 1] + accc[a][j][eh * 2 + 1];
                const float2 xb = *reinterpret_cast<const float2*>(xpb + idx);
                const float2 ho = *reinterpret_cast<const float2*>(hold + idx);
                const float hn0 = 0.5f * ho.x + 0.5f * tanhf(xb.x + r0);
                const float hn1 = 0.5f * ho.y + 0.5f * tanhf(xb.y + r1);
                *reinterpret_cast<float2*>(outF + idx) = make_float2(hn0, hn1);
                const __nv_bfloat16 b0 = __float2bfloat16(hn0);
                const __nv_bfloat16 b1 = __float2bfloat16(hn1);
                __nv_bfloat162 hiv, lov;
                hiv.x = b0; hiv.y = b1;
                lov.x = __float2bfloat16(hn0 - __bfloat162float(b0));
                lov.y = __float2bfloat16(hn1 - __bfloat162float(b1));
                *reinterpret_cast<__nv_bfloat162*>(outHi + idx) = hiv;
                *reinterpret_cast<__nv_bfloat162*>(outLo + idx) = lov;
            }
}

// ---------------- host ----------------
extern "C" void kernel_launch(void* const* d_in, const int* in_sizes, int n_in,
                              void* d_out, int out_size) {
    const float* x     = (const float*)d_in[0];
    const float* Winw  = (const float*)d_in[1];
    const float* Winb  = (const float*)d_in[2];
    const float* u     = (const float*)d_in[3];
    const float* W0    = (const float*)d_in[4];
    const float* b0    = (const float*)d_in[5];
    const float* W1    = (const float*)d_in[6];
    const float* b1    = (const float*)d_in[7];
    const float* W2    = (const float*)d_in[8];
    const float* b2    = (const float*)d_in[9];
    const float* headw = (const float*)d_in[10];
    const float* headb = (const float*)d_in[11];
    float* out = (float*)d_out;

    float *t, *s, *scal, *xp, *hA, *hB, *xpb;
    cudaGetSymbolAddress((void**)&t, g_t);
    cudaGetSymbolAddress((void**)&s, g_s);
    cudaGetSymbolAddress((void**)&scal, g_scal);
    cudaGetSymbolAddress((void**)&xp, g_xproj);
    cudaGetSymbolAddress((void**)&xpb, g_xpb);
    cudaGetSymbolAddress((void**)&hA, g_hA);
    cudaGetSymbolAddress((void**)&hB, g_hB);
    __nv_bfloat16 *W0h, *W0l, *W1h, *W1l, *W2h, *W2l, *Winh, *Winl, *Hdh, *Hdl;
    __nv_bfloat16 *xh, *xl, *hhA, *hlA, *hhB, *hlB;
    cudaGetSymbolAddress((void**)&W0h, g_W0hi);  cudaGetSymbolAddress((void**)&W0l, g_W0lo);
    cudaGetSymbolAddress((void**)&W1h, g_W1hi);  cudaGetSymbolAddress((void**)&W1l, g_W1lo);
    cudaGetSymbolAddress((void**)&W2h, g_W2hi);  cudaGetSymbolAddress((void**)&W2l, g_W2lo);
    cudaGetSymbolAddress((void**)&Winh, g_Winhi); cudaGetSymbolAddress((void**)&Winl, g_Winlo);
    cudaGetSymbolAddress((void**)&Hdh, g_Hdhi);  cudaGetSymbolAddress((void**)&Hdl, g_Hdlo);
    cudaGetSymbolAddress((void**)&xh, g_xhi);    cudaGetSymbolAddress((void**)&xl, g_xlo);
    cudaGetSymbolAddress((void**)&hhA, g_hhiA);  cudaGetSymbolAddress((void**)&hlA, g_hloA);
    cudaGetSymbolAddress((void**)&hhB, g_hhiB);  cudaGetSymbolAddress((void**)&hlB, g_hloB);

    cudaFuncSetAttribute(gemm_mma<0>, cudaFuncAttributeMaxDynamicSharedMemorySize, SMEM_BYTES);
    cudaFuncSetAttribute(gemm_mma<2>, cudaFuncAttributeMaxDynamicSharedMemorySize, SMEM_BYTES);
    cudaFuncSetAttribute(gemm_step, cudaFuncAttributeMaxDynamicSharedMemorySize, S_SMEM);

    // h0 = 0 (fp32 + bf16 hi/lo views)
    zero_kernel<<<(BATCH * D_H + 255) / 256, 256>>>(hA, BATCH * D_H);
    zero_kernel<<<(BATCH * D_H / 2 + 255) / 256, 256>>>((float*)hhA, BATCH * D_H / 2);
    zero_kernel<<<(BATCH * D_H / 2 + 255) / 256, 256>>>((float*)hlA, BATCH * D_H / 2);

    // hi/lo splits of static operands
    const int TB = 256;
    split_kernel<<<(D_H * D_H + TB - 1) / TB, TB>>>(W0, W0h, W0l, D_H * D_H);
    split_kernel<<<(D_H * D_H + TB - 1) / TB, TB>>>(W1, W1h, W1l, D_H * D_H);
    split_kernel<<<(D_H * D_H + TB - 1) / TB, TB>>>(W2, W2h, W2l, D_H * D_H);
    split_kernel<<<(D_H * D_IN + TB - 1) / TB, TB>>>(Winw, Winh, Winl, D_H * D_IN);
    split_kernel<<<(D_OUT * D_H + TB - 1) / TB, TB>>>(headw, Hdh, Hdl, D_OUT * D_H);
    split_kernel<<<(BATCH * D_IN + TB - 1) / TB, TB>>>(x, xh, xl, BATCH * D_IN);

    // spectral-norm scalar -> g_scal[1]
    matvec_t_kernel<<<D_IN / 256, 256>>>(Winw, u, t);
    reduce_t_kernel<<<1, 1024>>>(t, scal);
    matvec_s_kernel<<<64, 256>>>(Winw, t, scal, s);
    reduce_s_kernel<<<1, 1024>>>(s, scal);

    // x_proj = (x @ W_in^T)/sigma + b_in
    {
        dim3 grid(D_H / 64, BATCH / 64);
        gemm_mma<0><<<grid, 128, SMEM_BYTES>>>(xh, xl, Winh, Winl, Winb,
                                               xp, scal + 1, D_IN, D_H, D_H);
    }
    // xpb_l = xproj + b_l (fold per-layer bias once)
    const float* bs[3] = {b0, b1, b2};
    for (int l = 0; l < 3; l++)
        add_bias_kernel<<<(BATCH * D_H + TB - 1) / TB, TB>>>(
            xp, bs[l], xpb + (size_t)l * BATCH * D_H, BATCH * D_H);

    // 30 steps x 3 layers
    const __nv_bfloat16* Wh[3] = {W0h, W1h, W2h};
    const __nv_bfloat16* Wl[3] = {W0l, W1l, W2l};
    float *cur = hA, *nxt = hB;
    __nv_bfloat16 *curh = hhA, *curl = hlA, *nxth = hhB, *nxtl = hlB;
    dim3 gstep(D_H / 64, BATCH / 64);
    for (int st = 0; st < STEPS; st++) {
        for (int l = 0; l < 3; l++) {
            gemm_step<<<gstep, 256, S_SMEM>>>(curh, curl, Wh[l], Wl[l],
                                              xpb + (size_t)l * BATCH * D_H,
                                              cur, nxt, nxth, nxtl);
            float* tf = cur; cur = nxt; nxt = tf;
            __nv_bfloat16* th = curh; curh = nxth; nxth = th;
            __nv_bfloat16* tl = curl; curl = nxtl; nxtl = tl;
        }
    }

    // head: out = h @ head_w^T + head_b
    {
        dim3 grid((D_OUT + 63) / 64, BATCH / 64);
        gemm_mma<2><<<grid, 128, SMEM_BYTES>>>(curh, curl, Hdh, Hdl, headb,
                                               out, nullptr, D_H, D_OUT, D_OUT);
    }
}

// round 9
// speedup vs baseline: 1.1498x; 1.1498x over previous
#include <cuda_runtime.h>
#include <cuda_bf16.h>
#include <math.h>
#include <stdint.h>

#define D_IN   1024
#define D_H    2048
#define BATCH  256
#define D_OUT  1000
#define EPSV   1e-12f
#define STEPS  30

// ---- bf16 aux GEMM smem geometry (x_proj / head, 128-thread kernel) ----
#define ROW_B      144
#define TILE_A_HI  0
#define TILE_A_LO  9216
#define TILE_B_HI  18432
#define TILE_B_LO  27648
#define STAGE_BYTES 36864
#define SMEM_BYTES  (2 * STAGE_BYTES)

// ---- step GEMM smem: BK=128, 4 tiles of 64 rows x 256B pad to 272B, 3 stages ----
#define SROW     272
#define STILE    (64 * SROW)          // 17408
#define S_AH     0
#define S_AL     17408
#define S_BH     34816
#define S_BL     52224
#define S_STAGE  69632
#define S_SMEM   (3 * S_STAGE)        // 208896

// ---------------- device scratch (no allocations allowed) ----------------
__device__ float g_t[D_IN];
__device__ float g_s[D_H];
__device__ float g_scal[4];              // [1] = 1/sigma
__device__ float g_xpb[3][BATCH * D_H];  // xproj + bias_l, per layer
__device__ float g_hA[BATCH * D_H];
__device__ float g_hB[BATCH * D_H];

__device__ __nv_bfloat16 g_W0hi[D_H * D_H], g_W0lo[D_H * D_H];
__device__ __nv_bfloat16 g_W1hi[D_H * D_H], g_W1lo[D_H * D_H];
__device__ __nv_bfloat16 g_W2hi[D_H * D_H], g_W2lo[D_H * D_H];
__device__ __nv_bfloat16 g_Winhi[D_H * D_IN], g_Winlo[D_H * D_IN];
__device__ __nv_bfloat16 g_Hdhi[D_OUT * D_H], g_Hdlo[D_OUT * D_H];
__device__ __nv_bfloat16 g_xhi[BATCH * D_IN], g_xlo[BATCH * D_IN];
__device__ __nv_bfloat16 g_hhiA[BATCH * D_H], g_hloA[BATCH * D_H];
__device__ __nv_bfloat16 g_hhiB[BATCH * D_H], g_hloB[BATCH * D_H];

// ---------------- portable PTX helpers (sm_80+) ----------------
__device__ __forceinline__ uint32_t smem_u32(const void* p) {
    uint32_t a;
    asm("{ .reg .u64 t; cvta.to.shared.u64 t, %1; cvt.u32.u64 %0, t; }" : "=r"(a) : "l"(p));
    return a;
}
#define CP16(dst, src) asm volatile("cp.async.cg.shared.global [%0], [%1], 16;" :: "r"(dst), "l"(src))
#define CP_COMMIT()    asm volatile("cp.async.commit_group;" ::: "memory")
#define CP_WAIT(n)     asm volatile("cp.async.wait_group %0;" :: "n"(n) : "memory")

__device__ __forceinline__ void ldsm4(uint32_t* r, uint32_t addr) {
    asm volatile("ldmatrix.sync.aligned.m8n8.x4.shared.b16 {%0,%1,%2,%3}, [%4];"
        : "=r"(r[0]), "=r"(r[1]), "=r"(r[2]), "=r"(r[3]) : "r"(addr));
}
__device__ __forceinline__ void mma_bf16(float* c, const uint32_t* a, const uint32_t* b) {
    asm volatile("mma.sync.aligned.m16n8k16.row.col.f32.bf16.bf16.f32 "
        "{%0,%1,%2,%3}, {%4,%5,%6,%7}, {%8,%9}, {%0,%1,%2,%3};"
        : "+f"(c[0]), "+f"(c[1]), "+f"(c[2]), "+f"(c[3])
        : "r"(a[0]), "r"(a[1]), "r"(a[2]), "r"(a[3]), "r"(b[0]), "r"(b[1]));
}

// ---------------- prep: all splits + zeros in ONE launch ----------------
__device__ __forceinline__ void split_one(const float* __restrict__ src,
        __nv_bfloat16* __restrict__ hi, __nv_bfloat16* __restrict__ lo, int i) {
    float a = src[i];
    __nv_bfloat16 h = __float2bfloat16(a);
    hi[i] = h;
    lo[i] = __float2bfloat16(a - __bfloat162float(h));
}

__global__ void prep_kernel(const float* __restrict__ W0, const float* __restrict__ W1,
                            const float* __restrict__ W2, const float* __restrict__ Win,
                            const float* __restrict__ Hd, const float* __restrict__ x) {
    const int stride = gridDim.x * blockDim.x;
    const int t0 = blockIdx.x * blockDim.x + threadIdx.x;
    for (int i = t0; i < D_H * D_H; i += stride) {
        split_one(W0, g_W0hi, g_W0lo, i);
        split_one(W1, g_W1hi, g_W1lo, i);
        split_one(W2, g_W2hi, g_W2lo, i);
    }
    for (int i = t0; i < D_H * D_IN; i += stride) split_one(Win, g_Winhi, g_Winlo, i);
    for (int i = t0; i < D_OUT * D_H; i += stride) split_one(Hd, g_Hdhi, g_Hdlo, i);
    for (int i = t0; i < BATCH * D_IN; i += stride) split_one(x, g_xhi, g_xlo, i);
    for (int i = t0; i < BATCH * D_H; i += stride) {
        g_hA[i] = 0.0f;
        g_hhiA[i] = __float2bfloat16(0.0f);
        g_hloA[i] = __float2bfloat16(0.0f);
    }
}

// ---------------- spectral norm ----------------
__global__ void matvec_t_kernel(const float* __restrict__ W, const float* __restrict__ u,
                                float* __restrict__ t) {
    int j = blockIdx.x * blockDim.x + threadIdx.x;
    if (j >= D_IN) return;
    float acc = 0.0f;
#pragma unroll 4
    for (int i = 0; i < D_H; i++) acc = fmaf(W[(size_t)i * D_IN + j], u[i], acc);
    t[j] = acc;
}

// block-local ||t|| (redundant per block, cheap), then s[r] = t_norm . W[r,:]
__global__ void matvec_s_kernel(const float* __restrict__ W, const float* __restrict__ t,
                                float* __restrict__ s) {
    __shared__ float shw[8];
    const int tid = threadIdx.x;
    const int lane = tid & 31;
    const int w = tid >> 5;
    // local sum of squares over t[0..1023]
    float ss = 0.0f;
#pragma unroll
    for (int i = 0; i < 4; i++) {
        float v = t[tid + (i << 8)];
        ss = fmaf(v, v, ss);
    }
#pragma unroll
    for (int o = 16; o > 0; o >>= 1) ss += __shfl_xor_sync(0xffffffffu, ss, o);
    if (lane == 0) shw[w] = ss;
    __syncthreads();
    float tot = shw[lane & 7];
#pragma unroll
    for (int o = 4; o > 0; o >>= 1) tot += __shfl_xor_sync(0xffffffffu, tot, o);
    const float invn = 1.0f / (sqrtf(tot) + EPSV);

    const int gwarp = blockIdx.x * 8 + w;       // 512 warps total over 64 blocks
    for (int r = gwarp; r < D_H; r += 512) {
        const float* row = W + (size_t)r * D_IN;
        float acc = 0.0f;
        for (int j = lane; j < D_IN; j += 32) acc = fmaf(row[j], t[j], acc);
#pragma unroll
        for (int o = 16; o > 0; o >>= 1) acc += __shfl_xor_sync(0xffffffffu, acc, o);
        if (lane == 0) s[r] = acc * invn;
    }
}
__global__ void reduce_s_kernel(const float* __restrict__ s, float* __restrict__ scal) {
    __shared__ float sh[1024];
    int tid = threadIdx.x;
    float a = s[tid], b = s[tid + 1024];
    sh[tid] = a * a + b * b;
    __syncthreads();
    for (int o = 512; o > 0; o >>= 1) { if (tid < o) sh[tid] += sh[tid + o]; __syncthreads(); }
    if (tid == 0) { float q = sh[0]; scal[1] = (sqrtf(q) + EPSV) / q; }
}

// ================= bf16 3-pass aux GEMM =================
// MODE 0 (x_proj): v = acc*scale + bias[n]; writes xpb_l[idx] = v + b_l[n] for l=0..2
// MODE 2 (head):   outF = acc + bias[n], guarded n < NB
__device__ __forceinline__ void prefetch_chunk(uint32_t sb_u, char* sb_p, int k0,
        const __nv_bfloat16* __restrict__ Ahi, const __nv_bfloat16* __restrict__ Alo,
        const __nv_bfloat16* __restrict__ Bhi, const __nv_bfloat16* __restrict__ Blo,
        int K, int NB, int m0, int n0) {
    const int t = threadIdx.x;
#pragma unroll
    for (int r = 0; r < 4; r++) {
        const int idx = t + (r << 7);
        const int row = idx >> 3;
        const int c   = idx & 7;
        const uint32_t soff = (uint32_t)row * ROW_B + (c << 4);
        const size_t ga = (size_t)(m0 + row) * K + k0 + (c << 3);
        CP16(sb_u + TILE_A_HI + soff, Ahi + ga);
        CP16(sb_u + TILE_A_LO + soff, Alo + ga);
        const int gn = n0 + row;
        if (gn < NB) {
            const size_t gb = (size_t)gn * K + k0 + (c << 3);
            CP16(sb_u + TILE_B_HI + soff, Bhi + gb);
            CP16(sb_u + TILE_B_LO + soff, Blo + gb);
        } else {
            const uint4 z = make_uint4(0, 0, 0, 0);
            *reinterpret_cast<uint4*>(sb_p + TILE_B_HI + soff) = z;
            *reinterpret_cast<uint4*>(sb_p + TILE_B_LO + soff) = z;
        }
    }
}

template <int MODE>
__global__ void __launch_bounds__(128)
gemm_mma(const __nv_bfloat16* __restrict__ Ahi, const __nv_bfloat16* __restrict__ Alo,
         const __nv_bfloat16* __restrict__ Bhi, const __nv_bfloat16* __restrict__ Blo,
         const float* __restrict__ bias, float* __restrict__ outF,
         const float* __restrict__ scale_ptr, int K, int NB, int ldOut,
         const float* __restrict__ lb0, const float* __restrict__ lb1,
         const float* __restrict__ lb2, float* __restrict__ xpb) {
    extern __shared__ char smem[];
    const uint32_t sbase = smem_u32(smem);
    const int tid  = threadIdx.x;
    const int lane = tid & 31;
    const int wid  = tid >> 5;
    const int m0 = blockIdx.y * 64;
    const int n0 = blockIdx.x * 64;
    const int wm = (wid >> 1) << 5;
    const int wn = (wid & 1) << 5;
    const int NC = K >> 6;

    const int arow  = (lane & 7) | (((lane >> 3) & 1) << 3);
    const int akoff = ((lane >> 4) & 1) << 3;
    const int brow  = (lane & 7) | (((lane >> 4) & 1) << 3);
    const int bkoff = ((lane >> 3) & 1) << 3;

    float acc[2][4][4] = {};

    prefetch_chunk(sbase, smem, 0, Ahi, Alo, Bhi, Blo, K, NB, m0, n0);
    CP_COMMIT();

    for (int c = 0; c < NC; c++) {
        if (c + 1 < NC) {
            const int ns = (c + 1) & 1;
            prefetch_chunk(sbase + ns * STAGE_BYTES, smem + ns * STAGE_BYTES,
                           (c + 1) << 6, Ahi, Alo, Bhi, Blo, K, NB, m0, n0);
            CP_COMMIT();
            CP_WAIT(1);
        } else {
            CP_WAIT(0);
        }
        __syncthreads();

        const uint32_t st = sbase + (c & 1) * STAGE_BYTES;
#pragma unroll
        for (int kk = 0; kk < 4; kk++) {
            const int k0 = kk << 4;
            uint32_t ah[2][4], al[2][4], bh[2][4], bl[2][4];
#pragma unroll
            for (int a = 0; a < 2; a++) {
                const uint32_t off = (uint32_t)(wm + (a << 4) + arow) * ROW_B +
                                     ((k0 + akoff) << 1);
                ldsm4(ah[a], st + TILE_A_HI + off);
                ldsm4(al[a], st + TILE_A_LO + off);
            }
#pragma unroll
            for (int b = 0; b < 2; b++) {
                const uint32_t off = (uint32_t)(wn + (b << 4) + brow) * ROW_B +
                                     ((k0 + bkoff) << 1);
                ldsm4(bh[b], st + TILE_B_HI + off);
                ldsm4(bl[b], st + TILE_B_LO + off);
            }
#pragma unroll
            for (int a = 0; a < 2; a++)
#pragma unroll
                for (int j = 0; j < 4; j++)
                    mma_bf16(acc[a][j], ah[a], &bh[j >> 1][(j & 1) << 1]);
#pragma unroll
            for (int a = 0; a < 2; a++)
#pragma unroll
                for (int j = 0; j < 4; j++)
                    mma_bf16(acc[a][j], ah[a], &bl[j >> 1][(j & 1) << 1]);
#pragma unroll
            for (int a = 0; a < 2; a++)
#pragma unroll
                for (int j = 0; j < 4; j++)
                    mma_bf16(acc[a][j], al[a], &bh[j >> 1][(j & 1) << 1]);
        }
        __syncthreads();
    }

    const float scale = (MODE == 0) ? *scale_ptr : 1.0f;
    const int g  = lane >> 2;
    const int i2 = (lane & 3) << 1;
#pragma unroll
    for (int a = 0; a < 2; a++)
#pragma unroll
        for (int j = 0; j < 4; j++)
#pragma unroll
            for (int e = 0; e < 4; e++) {
                const int m = m0 + wm + (a << 4) + g + ((e >> 1) << 3);
                const int n = n0 + wn + (j << 3) + i2 + (e & 1);
                const float r = acc[a][j][e];
                if (MODE == 0) {
                    const float v = fmaf(r, scale, bias[n]);
                    const size_t idx = (size_t)m * D_H + n;
                    xpb[idx] = v + lb0[n];
                    xpb[(size_t)BATCH * D_H + idx] = v + lb1[n];
                    xpb[(size_t)2 * BATCH * D_H + idx] = v + lb2[n];
                } else {
                    if (n < NB) outF[(size_t)m * ldOut + n] = r + bias[n];
                }
            }
}

// ================= step GEMM: bf16 3-pass, 256 thr, BK=128, 3-stage cp.async =====
__device__ __forceinline__ void prefetch_step(uint32_t sb_u, int k0,
        const __nv_bfloat16* __restrict__ Ahi, const __nv_bfloat16* __restrict__ Alo,
        const __nv_bfloat16* __restrict__ Bhi, const __nv_bfloat16* __restrict__ Blo,
        int m0, int n0) {
    const int t = threadIdx.x;
#pragma unroll
    for (int r = 0; r < 4; r++) {
        const int idx = t + (r << 8);          // 0..1023
        const int row = idx >> 4;              // 0..63
        const int c   = idx & 15;              // 16B units, 256B row
        const uint32_t soff = (uint32_t)row * SROW + (c << 4);
        const size_t ga = (size_t)(m0 + row) * D_H + k0 + (c << 3);
        const size_t gb = (size_t)(n0 + row) * D_H + k0 + (c << 3);
        CP16(sb_u + S_AH + soff, Ahi + ga);
        CP16(sb_u + S_AL + soff, Alo + ga);
        CP16(sb_u + S_BH + soff, Bhi + gb);
        CP16(sb_u + S_BL + soff, Blo + gb);
    }
}

__global__ void __launch_bounds__(256)
gemm_step(const __nv_bfloat16* __restrict__ Ahi, const __nv_bfloat16* __restrict__ Alo,
          const __nv_bfloat16* __restrict__ Bhi, const __nv_bfloat16* __restrict__ Blo,
          const float* __restrict__ xpb, const float* __restrict__ hold,
          float* __restrict__ outF,
          __nv_bfloat16* __restrict__ outHi, __nv_bfloat16* __restrict__ outLo) {
    extern __shared__ char smem[];
    const uint32_t sbase = smem_u32(smem);
    const int tid  = threadIdx.x;
    const int lane = tid & 31;
    const int wid  = tid >> 5;
    const int m0 = blockIdx.y * 64;
    const int n0 = blockIdx.x * 64;
    const int wm = (wid >> 2) << 5;   // 0 or 32
    const int wn = (wid & 3) << 4;    // 0,16,32,48
    const int NC = D_H >> 7;          // 16 chunks of 128

    const int arow  = (lane & 7) | (((lane >> 3) & 1) << 3);
    const int akoff = ((lane >> 4) & 1) << 3;
    const int brow  = (lane & 7) | (((lane >> 4) & 1) << 3);
    const int bkoff = ((lane >> 3) & 1) << 3;

    float accm[2][2][4] = {};   // ah*bh
    float acc1[2][2][4] = {};   // ah*bl
    float acc2[2][2][4] = {};   // al*bh

    // prologue: 2 chunks in flight
    prefetch_step(sbase, 0, Ahi, Alo, Bhi, Blo, m0, n0);
    CP_COMMIT();
    prefetch_step(sbase + S_STAGE, 128, Ahi, Alo, Bhi, Blo, m0, n0);
    CP_COMMIT();

    int s = 0;
    for (int c = 0; c < NC; c++) {
        __syncthreads();   // all warps done reading the stage about to be overwritten
        if (c + 2 < NC) {
            const int ns = (s + 2 >= 3) ? (s - 1) : (s + 2);
            prefetch_step(sbase + ns * S_STAGE, (c + 2) << 7, Ahi, Alo, Bhi, Blo, m0, n0);
            CP_COMMIT();
            CP_WAIT(2);    // chunk c complete (2 newest may be in flight)
        } else if (c + 1 < NC) {
            CP_WAIT(1);
        } else {
            CP_WAIT(0);
        }
        __syncthreads();   // visibility of chunk c data to all warps

        const uint32_t st = sbase + s * S_STAGE;
#pragma unroll
        for (int kk = 0; kk < 8; kk++) {
            const int k0 = kk << 4;
            uint32_t ah[2][4], al[2][4], bh[4], bl[4];
#pragma unroll
            for (int a = 0; a < 2; a++) {
                const uint32_t off = (uint32_t)(wm + (a << 4) + arow) * SROW +
                                     ((k0 + akoff) << 1);
                ldsm4(ah[a], st + S_AH + off);
                ldsm4(al[a], st + S_AL + off);
            }
            {
                const uint32_t off = (uint32_t)(wn + brow) * SROW + ((k0 + bkoff) << 1);
                ldsm4(bh, st + S_BH + off);
                ldsm4(bl, st + S_BL + off);
            }
#pragma unroll
            for (int a = 0; a < 2; a++)
#pragma unroll
                for (int j = 0; j < 2; j++) {
                    mma_bf16(accm[a][j], ah[a], &bh[j << 1]);
                    mma_bf16(acc1[a][j], ah[a], &bl[j << 1]);
                    mma_bf16(acc2[a][j], al[a], &bh[j << 1]);
                }
        }
        s = (s + 1 >= 3) ? 0 : (s + 1);
    }

    // epilogue: vectorized 2-wide
    const int g  = lane >> 2;
    const int i2 = (lane & 3) << 1;
#pragma unroll
    for (int a = 0; a < 2; a++)
#pragma unroll
        for (int j = 0; j < 2; j++)
#pragma unroll
            for (int eh = 0; eh < 2; eh++) {
                const int m = m0 + wm + (a << 4) + g + (eh << 3);
                const int n = n0 + wn + (j << 3) + i2;
                const size_t idx = (size_t)m * D_H + n;
                const float r0 = accm[a][j][eh * 2 + 0] + acc1[a][j][eh * 2 + 0] +
                                 acc2[a][j][eh * 2 + 0];
                const float r1 = accm[a][j][eh * 2 + 1] + acc1[a][j][eh * 2 + 1] +
                                 acc2[a][j][eh * 2 + 1];
                const float2 xb = *reinterpret_cast<const float2*>(xpb + idx);
                const float2 ho = *reinterpret_cast<const float2*>(hold + idx);
                const float hn0 = 0.5f * ho.x + 0.5f * tanhf(xb.x + r0);
                const float hn1 = 0.5f * ho.y + 0.5f * tanhf(xb.y + r1);
                *reinterpret_cast<float2*>(outF + idx) = make_float2(hn0, hn1);
                const __nv_bfloat16 b0 = __float2bfloat16(hn0);
                const __nv_bfloat16 b1 = __float2bfloat16(hn1);
                __nv_bfloat162 hiv, lov;
                hiv.x = b0; hiv.y = b1;
                lov.x = __float2bfloat16(hn0 - __bfloat162float(b0));
                lov.y = __float2bfloat16(hn1 - __bfloat162float(b1));
                *reinterpret_cast<__nv_bfloat162*>(outHi + idx) = hiv;
                *reinterpret_cast<__nv_bfloat162*>(outLo + idx) = lov;
            }
}

// ---------------- host ----------------
extern "C" void kernel_launch(void* const* d_in, const int* in_sizes, int n_in,
                              void* d_out, int out_size) {
    const float* x     = (const float*)d_in[0];
    const float* Winw  = (const float*)d_in[1];
    const float* Winb  = (const float*)d_in[2];
    const float* u     = (const float*)d_in[3];
    const float* W0    = (const float*)d_in[4];
    const float* b0    = (const float*)d_in[5];
    const float* W1    = (const float*)d_in[6];
    const float* b1    = (const float*)d_in[7];
    const float* W2    = (const float*)d_in[8];
    const float* b2    = (const float*)d_in[9];
    const float* headw = (const float*)d_in[10];
    const float* headb = (const float*)d_in[11];
    float* out = (float*)d_out;

    float *t, *s, *scal, *hA, *hB, *xpb;
    cudaGetSymbolAddress((void**)&t, g_t);
    cudaGetSymbolAddress((void**)&s, g_s);
    cudaGetSymbolAddress((void**)&scal, g_scal);
    cudaGetSymbolAddress((void**)&xpb, g_xpb);
    cudaGetSymbolAddress((void**)&hA, g_hA);
    cudaGetSymbolAddress((void**)&hB, g_hB);
    __nv_bfloat16 *W0h, *W0l, *W1h, *W1l, *W2h, *W2l, *Winh, *Winl, *Hdh, *Hdl;
    __nv_bfloat16 *xh, *xl, *hhA, *hlA, *hhB, *hlB;
    cudaGetSymbolAddress((void**)&W0h, g_W0hi);  cudaGetSymbolAddress((void**)&W0l, g_W0lo);
    cudaGetSymbolAddress((void**)&W1h, g_W1hi);  cudaGetSymbolAddress((void**)&W1l, g_W1lo);
    cudaGetSymbolAddress((void**)&W2h, g_W2hi);  cudaGetSymbolAddress((void**)&W2l, g_W2lo);
    cudaGetSymbolAddress((void**)&Winh, g_Winhi); cudaGetSymbolAddress((void**)&Winl, g_Winlo);
    cudaGetSymbolAddress((void**)&Hdh, g_Hdhi);  cudaGetSymbolAddress((void**)&Hdl, g_Hdlo);
    cudaGetSymbolAddress((void**)&xh, g_xhi);    cudaGetSymbolAddress((void**)&xl, g_xlo);
    cudaGetSymbolAddress((void**)&hhA, g_hhiA);  cudaGetSymbolAddress((void**)&hlA, g_hloA);
    cudaGetSymbolAddress((void**)&hhB, g_hhiB);  cudaGetSymbolAddress((void**)&hlB, g_hloB);

    cudaFuncSetAttribute(gemm_mma<0>, cudaFuncAttributeMaxDynamicSharedMemorySize, SMEM_BYTES);
    cudaFuncSetAttribute(gemm_mma<2>, cudaFuncAttributeMaxDynamicSharedMemorySize, SMEM_BYTES);
    cudaFuncSetAttribute(gemm_step, cudaFuncAttributeMaxDynamicSharedMemorySize, S_SMEM);

    // launch 0: all splits + h zeros
    prep_kernel<<<592, 256>>>(W0, W1, W2, Winw, headw, x);

    // launches 1-3: spectral-norm scalar -> g_scal[1]
    matvec_t_kernel<<<D_IN / 256, 256>>>(Winw, u, t);
    matvec_s_kernel<<<64, 256>>>(Winw, t, s);
    reduce_s_kernel<<<1, 1024>>>(s, scal);

    // launch 4: x_proj (+ fused per-layer bias folds into xpb[0..2])
    {
        dim3 grid(D_H / 64, BATCH / 64);
        gemm_mma<0><<<grid, 128, SMEM_BYTES>>>(xh, xl, Winh, Winl, Winb,
                                               nullptr, scal + 1, D_IN, D_H, D_H,
                                               b0, b1, b2, xpb);
    }

    // launches 5..94: 30 steps x 3 layers (launch 5 = first gemm_step, ncu target)
    const __nv_bfloat16* Wh[3] = {W0h, W1h, W2h};
    const __nv_bfloat16* Wl[3] = {W0l, W1l, W2l};
    float *cur = hA, *nxt = hB;
    __nv_bfloat16 *curh = hhA, *curl = hlA, *nxth = hhB, *nxtl = hlB;
    dim3 gstep(D_H / 64, BATCH / 64);
    for (int st = 0; st < STEPS; st++) {
        for (int l = 0; l < 3; l++) {
            gemm_step<<<gstep, 256, S_SMEM>>>(curh, curl, Wh[l], Wl[l],
                                              xpb + (size_t)l * BATCH * D_H,
                                              cur, nxt, nxth, nxtl);
            float* tf = cur; cur = nxt; nxt = tf;
            __nv_bfloat16* th = curh; curh = nxth; nxth = th;
            __nv_bfloat16* tl = curl; curl = nxtl; nxtl = tl;
        }
    }

    // head: out = h @ head_w^T + head_b
    {
        dim3 grid((D_OUT + 63) / 64, BATCH / 64);
        gemm_mma<2><<<grid, 128, SMEM_BYTES>>>(curh, curl, Hdh, Hdl, headb,
                                               out, nullptr, D_H, D_OUT, D_OUT,
                                               nullptr, nullptr, nullptr, nullptr);
    }
}

// round 10
// speedup vs baseline: 1.4826x; 1.2894x over previous
#include <cuda_runtime.h>
#include <cuda_bf16.h>
#include <math.h>
#include <stdint.h>

#define D_IN   1024
#define D_H    2048
#define BATCH  256
#define D_OUT  1000
#define EPSV   1e-12f
#define STEPS  30

// ---- bf16 aux GEMM smem geometry (x_proj / head, 128-thread kernel) ----
#define ROW_B      144
#define TILE_A_HI  0
#define TILE_A_LO  9216
#define TILE_B_HI  18432
#define TILE_B_LO  27648
#define STAGE_BYTES 36864
#define SMEM_BYTES  (2 * STAGE_BYTES)

// ---- step GEMM smem: BK=128 panels, 4 tiles of 64 rows x 272B, 3 stages ----
#define SROW     272
#define STILE    17408                // 64 * 272
#define S_AH     0
#define S_AL     17408
#define S_BH     34816
#define S_BL     52224
#define S_STAGE  69632
#define S_DATA   128                  // mbarriers below
#define S_SMEM   (S_DATA + 3 * S_STAGE)   // 209024
#define S_TX     69632                // bytes per stage

// panel block byte offset for element (row-dim r, k-dim k) of a [.., 2048] matrix
#define NKCH     16                   // k chunks per 2048
__host__ __device__ __forceinline__ size_t pkoff(int r, int k) {
    return ((size_t)((r >> 6) * NKCH + (k >> 7))) * STILE +
           (size_t)(r & 63) * SROW + (size_t)((k & 127) << 1);
}

// ---------------- device scratch (no allocations allowed) ----------------
__device__ float g_t[D_IN];
__device__ float g_s[D_H];
__device__ float g_scal[4];              // [1] = 1/sigma
__device__ int   g_ticket;
__device__ float g_xpb[3][BATCH * D_H];  // xproj + bias_l
__device__ float g_hA[BATCH * D_H];
__device__ float g_hB[BATCH * D_H];

// packed (panel-layout) step operands
#define WPK_BYTES ((size_t)32 * NKCH * STILE)   // 8,912,896
#define HPK_BYTES ((size_t)4  * NKCH * STILE)   // 1,114,112
__device__ char g_W0hp[WPK_BYTES], g_W0lp[WPK_BYTES];
__device__ char g_W1hp[WPK_BYTES], g_W1lp[WPK_BYTES];
__device__ char g_W2hp[WPK_BYTES], g_W2lp[WPK_BYTES];
__device__ char g_hPhA[HPK_BYTES], g_hPlA[HPK_BYTES];
__device__ char g_hPhB[HPK_BYTES], g_hPlB[HPK_BYTES];

// plain bf16 splits (x_proj / head B operands)
__device__ __nv_bfloat16 g_Winhi[D_H * D_IN], g_Winlo[D_H * D_IN];
__device__ __nv_bfloat16 g_Hdhi[D_OUT * D_H], g_Hdlo[D_OUT * D_H];
__device__ __nv_bfloat16 g_xhi[BATCH * D_IN], g_xlo[BATCH * D_IN];

// ---------------- portable PTX helpers ----------------
__device__ __forceinline__ uint32_t smem_u32(const void* p) {
    uint32_t a;
    asm("{ .reg .u64 t; cvta.to.shared.u64 t, %1; cvt.u32.u64 %0, t; }" : "=r"(a) : "l"(p));
    return a;
}
#define CP16(dst, src) asm volatile("cp.async.cg.shared.global [%0], [%1], 16;" :: "r"(dst), "l"(src))
#define CP_COMMIT()    asm volatile("cp.async.commit_group;" ::: "memory")
#define CP_WAIT(n)     asm volatile("cp.async.wait_group %0;" :: "n"(n) : "memory")

#define MBAR_INIT(a, c) asm volatile("mbarrier.init.shared.b64 [%0], %1;" :: "r"(a), "r"(c) : "memory")
#define MBAR_EXPECT(a, bytes) \
    asm volatile("mbarrier.arrive.expect_tx.shared.b64 _, [%0], %1;" :: "r"(a), "r"(bytes) : "memory")
#define BULKT(dst, src, mbar) \
    asm volatile("cp.async.bulk.shared::cluster.global.mbarrier::complete_tx::bytes [%0], [%1], 17408, [%2];" \
        :: "r"(dst), "l"(src), "r"(mbar) : "memory")
#define MBAR_WAIT(mbar, parity) do {                                              \
    uint32_t _m = (mbar), _p = (parity), _d;                                      \
    asm volatile("{ .reg .pred p; mbarrier.try_wait.parity.acquire.cta.shared::cta.b64 p, [%1], %2; selp.b32 %0, 1, 0, p; }" \
        : "=r"(_d) : "r"(_m), "r"(_p) : "memory");                                \
    if (!_d) {                                                                    \
        asm volatile("{ .reg .pred P1; WL_%=: mbarrier.try_wait.parity.acquire.cta.shared::cta.b64 P1, [%0], %1, 0x989680; @P1 bra.uni WD_%=; bra.uni WL_%=; WD_%=: }" \
            :: "r"(_m), "r"(_p) : "memory");                                      \
    }                                                                             \
} while (0)

__device__ __forceinline__ void ldsm4(uint32_t* r, uint32_t addr) {
    asm volatile("ldmatrix.sync.aligned.m8n8.x4.shared.b16 {%0,%1,%2,%3}, [%4];"
        : "=r"(r[0]), "=r"(r[1]), "=r"(r[2]), "=r"(r[3]) : "r"(addr));
}
__device__ __forceinline__ void mma_bf16(float* c, const uint32_t* a, const uint32_t* b) {
    asm volatile("mma.sync.aligned.m16n8k16.row.col.f32.bf16.bf16.f32 "
        "{%0,%1,%2,%3}, {%4,%5,%6,%7}, {%8,%9}, {%0,%1,%2,%3};"
        : "+f"(c[0]), "+f"(c[1]), "+f"(c[2]), "+f"(c[3])
        : "r"(a[0]), "r"(a[1]), "r"(a[2]), "r"(a[3]), "r"(b[0]), "r"(b[1]));
}

// ---------------- prep: splits + packing + h0 zeros + matvec_t + ticket reset ----
__device__ __forceinline__ void split_plain(const float* __restrict__ src,
        __nv_bfloat16* __restrict__ hi, __nv_bfloat16* __restrict__ lo, int i) {
    float a = src[i];
    __nv_bfloat16 h = __float2bfloat16(a);
    hi[i] = h;
    lo[i] = __float2bfloat16(a - __bfloat162float(h));
}
__device__ __forceinline__ void split_pack(const float* __restrict__ src,
        char* __restrict__ hp, char* __restrict__ lp, int i) {
    const int r = i >> 11, k = i & 2047;
    const size_t off = pkoff(r, k);
    float a = src[i];
    __nv_bfloat16 h = __float2bfloat16(a);
    *reinterpret_cast<__nv_bfloat16*>(hp + off) = h;
    *reinterpret_cast<__nv_bfloat16*>(lp + off) =
        __float2bfloat16(a - __bfloat162float(h));
}

__global__ void prep_kernel(const float* __restrict__ W0, const float* __restrict__ W1,
                            const float* __restrict__ W2, const float* __restrict__ Win,
                            const float* __restrict__ Hd, const float* __restrict__ x,
                            const float* __restrict__ u) {
    const int stride = gridDim.x * blockDim.x;
    const int t0 = blockIdx.x * blockDim.x + threadIdx.x;
    if (t0 == 0) g_ticket = 0;
    for (int i = t0; i < D_H * D_H; i += stride) {
        split_pack(W0, g_W0hp, g_W0lp, i);
        split_pack(W1, g_W1hp, g_W1lp, i);
        split_pack(W2, g_W2hp, g_W2lp, i);
    }
    for (int i = t0; i < D_H * D_IN; i += stride) split_plain(Win, g_Winhi, g_Winlo, i);
    for (int i = t0; i < D_OUT * D_H; i += stride) split_plain(Hd, g_Hdhi, g_Hdlo, i);
    for (int i = t0; i < BATCH * D_IN; i += stride) split_plain(x, g_xhi, g_xlo, i);
    for (int i = t0; i < BATCH * D_H; i += stride) g_hA[i] = 0.0f;
    for (int i = t0; i < (int)(HPK_BYTES / 4); i += stride) {
        reinterpret_cast<uint32_t*>(g_hPhA)[i] = 0u;
        reinterpret_cast<uint32_t*>(g_hPlA)[i] = 0u;
    }
    // matvec_t: t[j] = sum_i Win[i,j] * u[i]
    for (int j = t0; j < D_IN; j += stride) {
        float acc = 0.0f;
#pragma unroll 4
        for (int i = 0; i < D_H; i++) acc = fmaf(Win[(size_t)i * D_IN + j], u[i], acc);
        g_t[j] = acc;
    }
}

// ---------------- sigma: matvec_s + final reduce, ticket-synced ----------------
__global__ void sigma_kernel(const float* __restrict__ W, const float* __restrict__ t,
                             float* __restrict__ s, float* __restrict__ scal) {
    __shared__ float shw[8];
    __shared__ int lastf;
    const int tid = threadIdx.x;
    const int lane = tid & 31;
    const int w = tid >> 5;
    float ss = 0.0f;
#pragma unroll
    for (int i = 0; i < 4; i++) {
        float v = t[tid + (i << 8)];
        ss = fmaf(v, v, ss);
    }
#pragma unroll
    for (int o = 16; o > 0; o >>= 1) ss += __shfl_xor_sync(0xffffffffu, ss, o);
    if (lane == 0) shw[w] = ss;
    __syncthreads();
    float tot = shw[lane & 7];
#pragma unroll
    for (int o = 4; o > 0; o >>= 1) tot += __shfl_xor_sync(0xffffffffu, tot, o);
    const float invn = 1.0f / (sqrtf(tot) + EPSV);

    const int gwarp = blockIdx.x * 8 + w;
    for (int r = gwarp; r < D_H; r += 512) {
        const float* row = W + (size_t)r * D_IN;
        float acc = 0.0f;
        for (int j = lane; j < D_IN; j += 32) acc = fmaf(row[j], t[j], acc);
#pragma unroll
        for (int o = 16; o > 0; o >>= 1) acc += __shfl_xor_sync(0xffffffffu, acc, o);
        if (lane == 0) s[r] = acc * invn;
    }
    __threadfence();
    if (tid == 0) lastf = (atomicAdd(&g_ticket, 1) == (int)gridDim.x - 1);
    __syncthreads();
    if (lastf) {
        __threadfence();
        float q = 0.0f;
        for (int i = tid; i < D_H; i += 256) { float v = s[i]; q = fmaf(v, v, q); }
#pragma unroll
        for (int o = 16; o > 0; o >>= 1) q += __shfl_xor_sync(0xffffffffu, q, o);
        if (lane == 0) shw[w] = q;
        __syncthreads();
        if (tid == 0) {
            float Q = 0.0f;
#pragma unroll
            for (int i = 0; i < 8; i++) Q += shw[i];
            scal[1] = (sqrtf(Q) + EPSV) / Q;
        }
    }
}

// ================= bf16 3-pass aux GEMM =================
// MODE 0 (x_proj, A plain): xpb_l = acc*scale + bias + b_l
// MODE 2 (head, A packed):  outF = acc + bias, guard n < NB
template <int AP>
__device__ __forceinline__ void prefetch_chunk(uint32_t sb_u, char* sb_p, int k0,
        const void* Ahi, const void* Alo,
        const __nv_bfloat16* __restrict__ Bhi, const __nv_bfloat16* __restrict__ Blo,
        int K, int NB, int m0, int n0) {
    const int t = threadIdx.x;
#pragma unroll
    for (int r = 0; r < 4; r++) {
        const int idx = t + (r << 7);
        const int row = idx >> 3;
        const int c   = idx & 7;
        const uint32_t soff = (uint32_t)row * ROW_B + (c << 4);
        const void *pa, *pl;
        if (AP == 0) {
            const size_t ga = (size_t)(m0 + row) * K + k0 + (c << 3);
            pa = (const __nv_bfloat16*)Ahi + ga;
            pl = (const __nv_bfloat16*)Alo + ga;
        } else {
            const size_t gb = ((size_t)((m0 >> 6) * NKCH + (k0 >> 7))) * STILE +
                              (size_t)row * SROW + ((k0 & 127) << 1) + (c << 4);
            pa = (const char*)Ahi + gb;
            pl = (const char*)Alo + gb;
        }
        CP16(sb_u + TILE_A_HI + soff, pa);
        CP16(sb_u + TILE_A_LO + soff, pl);
        const int gn = n0 + row;
        if (gn < NB) {
            const size_t gb2 = (size_t)gn * K + k0 + (c << 3);
            CP16(sb_u + TILE_B_HI + soff, Bhi + gb2);
            CP16(sb_u + TILE_B_LO + soff, Blo + gb2);
        } else {
            const uint4 z = make_uint4(0, 0, 0, 0);
            *reinterpret_cast<uint4*>(sb_p + TILE_B_HI + soff) = z;
            *reinterpret_cast<uint4*>(sb_p + TILE_B_LO + soff) = z;
        }
    }
}

template <int MODE, int AP>
__global__ void __launch_bounds__(128)
gemm_mma(const void* Ahi, const void* Alo,
         const __nv_bfloat16* __restrict__ Bhi, const __nv_bfloat16* __restrict__ Blo,
         const float* __restrict__ bias, float* __restrict__ outF,
         const float* __restrict__ scale_ptr, int K, int NB, int ldOut,
         const float* __restrict__ lb0, const float* __restrict__ lb1,
         const float* __restrict__ lb2, float* __restrict__ xpb) {
    extern __shared__ char smem[];
    const uint32_t sbase = smem_u32(smem);
    const int tid  = threadIdx.x;
    const int lane = tid & 31;
    const int wid  = tid >> 5;
    const int m0 = blockIdx.y * 64;
    const int n0 = blockIdx.x * 64;
    const int wm = (wid >> 1) << 5;
    const int wn = (wid & 1) << 5;
    const int NC = K >> 6;

    const int arow  = (lane & 7) | (((lane >> 3) & 1) << 3);
    const int akoff = ((lane >> 4) & 1) << 3;
    const int brow  = (lane & 7) | (((lane >> 4) & 1) << 3);
    const int bkoff = ((lane >> 3) & 1) << 3;

    float acc[2][4][4] = {};

    prefetch_chunk<AP>(sbase, smem, 0, Ahi, Alo, Bhi, Blo, K, NB, m0, n0);
    CP_COMMIT();

    for (int c = 0; c < NC; c++) {
        if (c + 1 < NC) {
            const int ns = (c + 1) & 1;
            prefetch_chunk<AP>(sbase + ns * STAGE_BYTES, smem + ns * STAGE_BYTES,
                               (c + 1) << 6, Ahi, Alo, Bhi, Blo, K, NB, m0, n0);
            CP_COMMIT();
            CP_WAIT(1);
        } else {
            CP_WAIT(0);
        }
        __syncthreads();

        const uint32_t st = sbase + (c & 1) * STAGE_BYTES;
#pragma unroll
        for (int kk = 0; kk < 4; kk++) {
            const int k0 = kk << 4;
            uint32_t ah[2][4], al[2][4], bh[2][4], bl[2][4];
#pragma unroll
            for (int a = 0; a < 2; a++) {
                const uint32_t off = (uint32_t)(wm + (a << 4) + arow) * ROW_B +
                                     ((k0 + akoff) << 1);
                ldsm4(ah[a], st + TILE_A_HI + off);
                ldsm4(al[a], st + TILE_A_LO + off);
            }
#pragma unroll
            for (int b = 0; b < 2; b++) {
                const uint32_t off = (uint32_t)(wn + (b << 4) + brow) * ROW_B +
                                     ((k0 + bkoff) << 1);
                ldsm4(bh[b], st + TILE_B_HI + off);
                ldsm4(bl[b], st + TILE_B_LO + off);
            }
#pragma unroll
            for (int a = 0; a < 2; a++)
#pragma unroll
                for (int j = 0; j < 4; j++)
                    mma_bf16(acc[a][j], ah[a], &bh[j >> 1][(j & 1) << 1]);
#pragma unroll
            for (int a = 0; a < 2; a++)
#pragma unroll
                for (int j = 0; j < 4; j++)
                    mma_bf16(acc[a][j], ah[a], &bl[j >> 1][(j & 1) << 1]);
#pragma unroll
            for (int a = 0; a < 2; a++)
#pragma unroll
                for (int j = 0; j < 4; j++)
                    mma_bf16(acc[a][j], al[a], &bh[j >> 1][(j & 1) << 1]);
        }
        __syncthreads();
    }

    const float scale = (MODE == 0) ? *scale_ptr : 1.0f;
    const int g  = lane >> 2;
    const int i2 = (lane & 3) << 1;
#pragma unroll
    for (int a = 0; a < 2; a++)
#pragma unroll
        for (int j = 0; j < 4; j++)
#pragma unroll
            for (int e = 0; e < 4; e++) {
                const int m = m0 + wm + (a << 4) + g + ((e >> 1) << 3);
                const int n = n0 + wn + (j << 3) + i2 + (e & 1);
                const float r = acc[a][j][e];
                if (MODE == 0) {
                    const float v = fmaf(r, scale, bias[n]);
                    const size_t idx = (size_t)m * D_H + n;
                    xpb[idx] = v + lb0[n];
                    xpb[(size_t)BATCH * D_H + idx] = v + lb1[n];
                    xpb[(size_t)2 * BATCH * D_H + idx] = v + lb2[n];
                } else {
                    if (n < NB) outF[(size_t)m * ldOut + n] = r + bias[n];
                }
            }
}

// ================= step GEMM: bf16 3-pass, 4x cp.async.bulk per chunk =============
__device__ __forceinline__ void issue_chunk(uint32_t st_u, uint32_t mbar, int chunk,
        const char* __restrict__ AH, const char* __restrict__ AL,
        const char* __restrict__ BH, const char* __restrict__ BL, int mt, int nt) {
    const size_t ab = ((size_t)(mt * NKCH + chunk)) * STILE;
    const size_t bb = ((size_t)(nt * NKCH + chunk)) * STILE;
    BULKT(st_u + S_AH, AH + ab, mbar);
    BULKT(st_u + S_AL, AL + ab, mbar);
    BULKT(st_u + S_BH, BH + bb, mbar);
    BULKT(st_u + S_BL, BL + bb, mbar);
}

__global__ void __launch_bounds__(256)
gemm_step(const char* __restrict__ AH, const char* __restrict__ AL,
          const char* __restrict__ BH, const char* __restrict__ BL,
          const float* __restrict__ xpb, const float* __restrict__ hold,
          float* __restrict__ outF,
          char* __restrict__ outHp, char* __restrict__ outLp) {
    extern __shared__ char smem[];
    const uint32_t sbase = smem_u32(smem);
    const uint32_t data0 = sbase + S_DATA;
    const int tid  = threadIdx.x;
    const int lane = tid & 31;
    const int wid  = tid >> 5;
    const int mt = blockIdx.y;        // 0..3
    const int nt = blockIdx.x;        // 0..31
    const int m0 = mt << 6;
    const int n0 = nt << 6;
    const int wm = (wid >> 2) << 5;
    const int wn = (wid & 3) << 4;
    const int NC = NKCH;              // 16 chunks of 128

    const int arow  = (lane & 7) | (((lane >> 3) & 1) << 3);
    const int akoff = ((lane >> 4) & 1) << 3;
    const int brow  = (lane & 7) | (((lane >> 4) & 1) << 3);
    const int bkoff = ((lane >> 3) & 1) << 3;

    float accm[2][2][4] = {};
    float acc1[2][2][4] = {};
    float acc2[2][2][4] = {};

    if (tid == 0) {
        MBAR_INIT(sbase + 0, 1);
        MBAR_INIT(sbase + 16, 1);
        MBAR_INIT(sbase + 32, 1);
    }
    __syncthreads();
    if (tid == 0) {
        MBAR_EXPECT(sbase + 0, S_TX);
        issue_chunk(data0, sbase + 0, 0, AH, AL, BH, BL, mt, nt);
        MBAR_EXPECT(sbase + 16, S_TX);
        issue_chunk(data0 + S_STAGE, sbase + 16, 1, AH, AL, BH, BL, mt, nt);
    }

    int ph0 = 0, ph1 = 0, ph2 = 0;
    int s = 0;
    for (int c = 0; c < NC; c++) {
        if (c + 2 < NC) {
            __syncthreads();   // everyone finished reading the stage being reused
            if (tid == 0) {
                const int s2 = (s + 2 >= 3) ? (s - 1) : (s + 2);
                MBAR_EXPECT(sbase + (s2 << 4), S_TX);
                issue_chunk(data0 + s2 * S_STAGE, sbase + (s2 << 4), c + 2,
                            AH, AL, BH, BL, mt, nt);
            }
        }
        if (s == 0)      { MBAR_WAIT(sbase + 0,  ph0); ph0 ^= 1; }
        else if (s == 1) { MBAR_WAIT(sbase + 16, ph1); ph1 ^= 1; }
        else             { MBAR_WAIT(sbase + 32, ph2); ph2 ^= 1; }

        const uint32_t st = data0 + s * S_STAGE;
#pragma unroll
        for (int kk = 0; kk < 8; kk++) {
            const int k0 = kk << 4;
            uint32_t ah[2][4], al[2][4], bh[4], bl[4];
#pragma unroll
            for (int a = 0; a < 2; a++) {
                const uint32_t off = (uint32_t)(wm + (a << 4) + arow) * SROW +
                                     ((k0 + akoff) << 1);
                ldsm4(ah[a], st + S_AH + off);
                ldsm4(al[a], st + S_AL + off);
            }
            {
                const uint32_t off = (uint32_t)(wn + brow) * SROW + ((k0 + bkoff) << 1);
                ldsm4(bh, st + S_BH + off);
                ldsm4(bl, st + S_BL + off);
            }
#pragma unroll
            for (int a = 0; a < 2; a++)
#pragma unroll
                for (int j = 0; j < 2; j++) {
                    mma_bf16(accm[a][j], ah[a], &bh[j << 1]);
                    mma_bf16(acc1[a][j], ah[a], &bl[j << 1]);
                    mma_bf16(acc2[a][j], al[a], &bh[j << 1]);
                }
        }
        s = (s + 1 >= 3) ? 0 : (s + 1);
    }

    // epilogue: fp32 h (plain) + bf16 hi/lo limbs (packed panel layout)
    const int g  = lane >> 2;
    const int i2 = (lane & 3) << 1;
#pragma unroll
    for (int a = 0; a < 2; a++)
#pragma unroll
        for (int j = 0; j < 2; j++)
#pragma unroll
            for (int eh = 0; eh < 2; eh++) {
                const int m = m0 + wm + (a << 4) + g + (eh << 3);
                const int n = n0 + wn + (j << 3) + i2;
                const size_t idx = (size_t)m * D_H + n;
                const float r0 = accm[a][j][eh * 2 + 0] + acc1[a][j][eh * 2 + 0] +
                                 acc2[a][j][eh * 2 + 0];
                const float r1 = accm[a][j][eh * 2 + 1] + acc1[a][j][eh * 2 + 1] +
                                 acc2[a][j][eh * 2 + 1];
                const float2 xb = *reinterpret_cast<const float2*>(xpb + idx);
                const float2 ho = *reinterpret_cast<const float2*>(hold + idx);
                const float hn0 = 0.5f * ho.x + 0.5f * tanhf(xb.x + r0);
                const float hn1 = 0.5f * ho.y + 0.5f * tanhf(xb.y + r1);
                *reinterpret_cast<float2*>(outF + idx) = make_float2(hn0, hn1);
                const __nv_bfloat16 b0 = __float2bfloat16(hn0);
                const __nv_bfloat16 b1 = __float2bfloat16(hn1);
                __nv_bfloat162 hiv, lov;
                hiv.x = b0; hiv.y = b1;
                lov.x = __float2bfloat16(hn0 - __bfloat162float(b0));
                lov.y = __float2bfloat16(hn1 - __bfloat162float(b1));
                const size_t pidx = pkoff(m, n);
                *reinterpret_cast<__nv_bfloat162*>(outHp + pidx) = hiv;
                *reinterpret_cast<__nv_bfloat162*>(outLp + pidx) = lov;
            }
}

// ---------------- host ----------------
extern "C" void kernel_launch(void* const* d_in, const int* in_sizes, int n_in,
                              void* d_out, int out_size) {
    const float* x     = (const float*)d_in[0];
    const float* Winw  = (const float*)d_in[1];
    const float* Winb  = (const float*)d_in[2];
    const float* u     = (const float*)d_in[3];
    const float* W0    = (const float*)d_in[4];
    const float* b0    = (const float*)d_in[5];
    const float* W1    = (const float*)d_in[6];
    const float* b1    = (const float*)d_in[7];
    const float* W2    = (const float*)d_in[8];
    const float* b2    = (const float*)d_in[9];
    const float* headw = (const float*)d_in[10];
    const float* headb = (const float*)d_in[11];
    float* out = (float*)d_out;

    float *t, *s, *scal, *hA, *hB, *xpb;
    cudaGetSymbolAddress((void**)&t, g_t);
    cudaGetSymbolAddress((void**)&s, g_s);
    cudaGetSymbolAddress((void**)&scal, g_scal);
    cudaGetSymbolAddress((void**)&xpb, g_xpb);
    cudaGetSymbolAddress((void**)&hA, g_hA);
    cudaGetSymbolAddress((void**)&hB, g_hB);
    char *W0hp, *W0lp, *W1hp, *W1lp, *W2hp, *W2lp, *hPhA, *hPlA, *hPhB, *hPlB;
    cudaGetSymbolAddress((void**)&W0hp, g_W0hp); cudaGetSymbolAddress((void**)&W0lp, g_W0lp);
    cudaGetSymbolAddress((void**)&W1hp, g_W1hp); cudaGetSymbolAddress((void**)&W1lp, g_W1lp);
    cudaGetSymbolAddress((void**)&W2hp, g_W2hp); cudaGetSymbolAddress((void**)&W2lp, g_W2lp);
    cudaGetSymbolAddress((void**)&hPhA, g_hPhA); cudaGetSymbolAddress((void**)&hPlA, g_hPlA);
    cudaGetSymbolAddress((void**)&hPhB, g_hPhB); cudaGetSymbolAddress((void**)&hPlB, g_hPlB);
    __nv_bfloat16 *Winh, *Winl, *Hdh, *Hdl, *xh, *xl;
    cudaGetSymbolAddress((void**)&Winh, g_Winhi); cudaGetSymbolAddress((void**)&Winl, g_Winlo);
    cudaGetSymbolAddress((void**)&Hdh, g_Hdhi);   cudaGetSymbolAddress((void**)&Hdl, g_Hdlo);
    cudaGetSymbolAddress((void**)&xh, g_xhi);     cudaGetSymbolAddress((void**)&xl, g_xlo);

    cudaFuncSetAttribute(gemm_mma<0, 0>, cudaFuncAttributeMaxDynamicSharedMemorySize, SMEM_BYTES);
    cudaFuncSetAttribute(gemm_mma<2, 1>, cudaFuncAttributeMaxDynamicSharedMemorySize, SMEM_BYTES);
    cudaFuncSetAttribute(gemm_step, cudaFuncAttributeMaxDynamicSharedMemorySize, S_SMEM);

    // 0: prep (splits + packing + zeros + matvec_t + ticket reset)
    prep_kernel<<<592, 256>>>(W0, W1, W2, Winw, headw, x, u);
    // 1: sigma (matvec_s + reduce, ticket-synced)
    sigma_kernel<<<64, 256>>>(Winw, t, s, scal);
    // 2: x_proj (writes xpb[0..2] with per-layer bias folded)
    {
        dim3 grid(D_H / 64, BATCH / 64);
        gemm_mma<0, 0><<<grid, 128, SMEM_BYTES>>>(xh, xl, Winh, Winl, Winb,
                                                  nullptr, scal + 1, D_IN, D_H, D_H,
                                                  b0, b1, b2, xpb);
    }
    // 3..92: 30 steps x 3 layers (index 3 = first gemm_step -> ncu target)
    const char* Whp[3] = {W0hp, W1hp, W2hp};
    const char* Wlp[3] = {W0lp, W1lp, W2lp};
    float *cur = hA, *nxt = hB;
    char *curh = hPhA, *curl = hPlA, *nxth = hPhB, *nxtl = hPlB;
    dim3 gstep(D_H / 64, BATCH / 64);
    for (int st = 0; st < STEPS; st++) {
        for (int l = 0; l < 3; l++) {
            gemm_step<<<gstep, 256, S_SMEM>>>(curh, curl, Whp[l], Wlp[l],
                                              xpb + (size_t)l * BATCH * D_H,
                                              cur, nxt, nxth, nxtl);
            float* tf = cur; cur = nxt; nxt = tf;
            char* th = curh; curh = nxth; nxth = th;
            char* tl = curl; curl = nxtl; nxtl = tl;
        }
    }
    // 93: head (A = packed final h)
    {
        dim3 grid((D_OUT + 63) / 64, BATCH / 64);
        gemm_mma<2, 1><<<grid, 128, SMEM_BYTES>>>(curh, curl, Hdh, Hdl, headb,
                                                  out, nullptr, D_H, D_OUT, D_OUT,
                                                  nullptr, nullptr, nullptr, nullptr);
    }
}

// round 11
// speedup vs baseline: 1.4895x; 1.0047x over previous
#include <cuda_runtime.h>
#include <cuda_bf16.h>
#include <math.h>
#include <stdint.h>

#define D_IN   1024
#define D_H    2048
#define BATCH  256
#define D_OUT  1000
#define EPSV   1e-12f
#define STEPS  30

// ---- bf16 aux GEMM smem geometry (x_proj / head, 128-thread kernel) ----
#define ROW_B      144
#define TILE_A_HI  0
#define TILE_A_LO  9216
#define TILE_B_HI  18432
#define TILE_B_LO  27648
#define STAGE_BYTES 36864
#define SMEM_BYTES  (2 * STAGE_BYTES)

// ---- step GEMM smem: BK=128 panels, 4 tiles of 64 rows x 272B, 3 stages ----
#define SROW     272
#define STILE    17408                // 64 * 272
#define S_AH     0
#define S_AL     17408
#define S_BH     34816
#define S_BL     52224
#define S_STAGE  69632
#define S_DATA   128                  // mbarriers below
#define S_SMEM   (S_DATA + 3 * S_STAGE)   // 209024
#define S_TX     69632                // bytes per stage

// panel block byte offset for element (row-dim r, k-dim k) of a [.., 2048] matrix
#define NKCH     16                   // k chunks per 2048
__host__ __device__ __forceinline__ size_t pkoff(int r, int k) {
    return ((size_t)((r >> 6) * NKCH + (k >> 7))) * STILE +
           (size_t)(r & 63) * SROW + (size_t)((k & 127) << 1);
}

// ---------------- device scratch (no allocations allowed) ----------------
__device__ float g_t[D_IN];
__device__ float g_s[D_H];
__device__ float g_scal[4];              // [1] = 1/sigma
__device__ int   g_ticket;
__device__ float g_xpb[3][BATCH * D_H];  // xproj + bias_l
__device__ float g_hA[BATCH * D_H];
__device__ float g_hB[BATCH * D_H];

// packed (panel-layout) step operands
#define WPK_BYTES ((size_t)32 * NKCH * STILE)   // 8,912,896
#define HPK_BYTES ((size_t)4  * NKCH * STILE)   // 1,114,112
__device__ char g_W0hp[WPK_BYTES], g_W0lp[WPK_BYTES];
__device__ char g_W1hp[WPK_BYTES], g_W1lp[WPK_BYTES];
__device__ char g_W2hp[WPK_BYTES], g_W2lp[WPK_BYTES];
__device__ char g_hPhA[HPK_BYTES], g_hPlA[HPK_BYTES];
__device__ char g_hPhB[HPK_BYTES], g_hPlB[HPK_BYTES];

// plain bf16 splits (x_proj / head B operands)
__device__ __nv_bfloat16 g_Winhi[D_H * D_IN], g_Winlo[D_H * D_IN];
__device__ __nv_bfloat16 g_Hdhi[D_OUT * D_H], g_Hdlo[D_OUT * D_H];
__device__ __nv_bfloat16 g_xhi[BATCH * D_IN], g_xlo[BATCH * D_IN];

// ---------------- portable PTX helpers ----------------
__device__ __forceinline__ uint32_t smem_u32(const void* p) {
    uint32_t a;
    asm("{ .reg .u64 t; cvta.to.shared.u64 t, %1; cvt.u32.u64 %0, t; }" : "=r"(a) : "l"(p));
    return a;
}
#define CP16(dst, src) asm volatile("cp.async.cg.shared.global [%0], [%1], 16;" :: "r"(dst), "l"(src))
#define CP_COMMIT()    asm volatile("cp.async.commit_group;" ::: "memory")
#define CP_WAIT(n)     asm volatile("cp.async.wait_group %0;" :: "n"(n) : "memory")

#define MBAR_INIT(a, c) asm volatile("mbarrier.init.shared.b64 [%0], %1;" :: "r"(a), "r"(c) : "memory")
#define MBAR_EXPECT(a, bytes) \
    asm volatile("mbarrier.arrive.expect_tx.shared.b64 _, [%0], %1;" :: "r"(a), "r"(bytes) : "memory")
#define BULKT(dst, src, mbar) \
    asm volatile("cp.async.bulk.shared::cluster.global.mbarrier::complete_tx::bytes [%0], [%1], 17408, [%2];" \
        :: "r"(dst), "l"(src), "r"(mbar) : "memory")
#define MBAR_WAIT(mbar, parity) do {                                              \
    uint32_t _m = (mbar), _p = (parity), _d;                                      \
    asm volatile("{ .reg .pred p; mbarrier.try_wait.parity.acquire.cta.shared::cta.b64 p, [%1], %2; selp.b32 %0, 1, 0, p; }" \
        : "=r"(_d) : "r"(_m), "r"(_p) : "memory");                                \
    if (!_d) {                                                                    \
        asm volatile("{ .reg .pred P1; WL_%=: mbarrier.try_wait.parity.acquire.cta.shared::cta.b64 P1, [%0], %1, 0x989680; @P1 bra.uni WD_%=; bra.uni WL_%=; WD_%=: }" \
            :: "r"(_m), "r"(_p) : "memory");                                      \
    }                                                                             \
} while (0)

__device__ __forceinline__ void ldsm4(uint32_t* r, uint32_t addr) {
    asm volatile("ldmatrix.sync.aligned.m8n8.x4.shared.b16 {%0,%1,%2,%3}, [%4];"
        : "=r"(r[0]), "=r"(r[1]), "=r"(r[2]), "=r"(r[3]) : "r"(addr));
}
__device__ __forceinline__ void mma_bf16(float* c, const uint32_t* a, const uint32_t* b) {
    asm volatile("mma.sync.aligned.m16n8k16.row.col.f32.bf16.bf16.f32 "
        "{%0,%1,%2,%3}, {%4,%5,%6,%7}, {%8,%9}, {%0,%1,%2,%3};"
        : "+f"(c[0]), "+f"(c[1]), "+f"(c[2]), "+f"(c[3])
        : "r"(a[0]), "r"(a[1]), "r"(a[2]), "r"(a[3]), "r"(b[0]), "r"(b[1]));
}

// ---------------- prep: splits + packing + h0 zeros + matvec_t + ticket reset ----
__device__ __forceinline__ void split_plain(const float* __restrict__ src,
        __nv_bfloat16* __restrict__ hi, __nv_bfloat16* __restrict__ lo, int i) {
    float a = src[i];
    __nv_bfloat16 h = __float2bfloat16(a);
    hi[i] = h;
    lo[i] = __float2bfloat16(a - __bfloat162float(h));
}
__device__ __forceinline__ void split_pack(const float* __restrict__ src,
        char* __restrict__ hp, char* __restrict__ lp, int i) {
    const int r = i >> 11, k = i & 2047;
    const size_t off = pkoff(r, k);
    float a = src[i];
    __nv_bfloat16 h = __float2bfloat16(a);
    *reinterpret_cast<__nv_bfloat16*>(hp + off) = h;
    *reinterpret_cast<__nv_bfloat16*>(lp + off) =
        __float2bfloat16(a - __bfloat162float(h));
}

__global__ void prep_kernel(const float* __restrict__ W0, const float* __restrict__ W1,
                            const float* __restrict__ W2, const float* __restrict__ Win,
                            const float* __restrict__ Hd, const float* __restrict__ x,
                            const float* __restrict__ u) {
    const int stride = gridDim.x * blockDim.x;
    const int t0 = blockIdx.x * blockDim.x + threadIdx.x;
    if (t0 == 0) g_ticket = 0;
    for (int i = t0; i < D_H * D_H; i += stride) {
        split_pack(W0, g_W0hp, g_W0lp, i);
        split_pack(W1, g_W1hp, g_W1lp, i);
        split_pack(W2, g_W2hp, g_W2lp, i);
    }
    for (int i = t0; i < D_H * D_IN; i += stride) split_plain(Win, g_Winhi, g_Winlo, i);
    for (int i = t0; i < D_OUT * D_H; i += stride) split_plain(Hd, g_Hdhi, g_Hdlo, i);
    for (int i = t0; i < BATCH * D_IN; i += stride) split_plain(x, g_xhi, g_xlo, i);
    for (int i = t0; i < BATCH * D_H; i += stride) g_hA[i] = 0.0f;
    for (int i = t0; i < (int)(HPK_BYTES / 4); i += stride) {
        reinterpret_cast<uint32_t*>(g_hPhA)[i] = 0u;
        reinterpret_cast<uint32_t*>(g_hPlA)[i] = 0u;
    }
    for (int j = t0; j < D_IN; j += stride) {
        float acc = 0.0f;
#pragma unroll 4
        for (int i = 0; i < D_H; i++) acc = fmaf(Win[(size_t)i * D_IN + j], u[i], acc);
        g_t[j] = acc;
    }
}

// ---------------- sigma: matvec_s + final reduce, ticket-synced ----------------
__global__ void sigma_kernel(const float* __restrict__ W, const float* __restrict__ t,
                             float* __restrict__ s, float* __restrict__ scal) {
    __shared__ float shw[8];
    __shared__ int lastf;
    const int tid = threadIdx.x;
    const int lane = tid & 31;
    const int w = tid >> 5;
    float ss = 0.0f;
#pragma unroll
    for (int i = 0; i < 4; i++) {
        float v = t[tid + (i << 8)];
        ss = fmaf(v, v, ss);
    }
#pragma unroll
    for (int o = 16; o > 0; o >>= 1) ss += __shfl_xor_sync(0xffffffffu, ss, o);
    if (lane == 0) shw[w] = ss;
    __syncthreads();
    float tot = shw[lane & 7];
#pragma unroll
    for (int o = 4; o > 0; o >>= 1) tot += __shfl_xor_sync(0xffffffffu, tot, o);
    const float invn = 1.0f / (sqrtf(tot) + EPSV);

    const int gwarp = blockIdx.x * 8 + w;
    for (int r = gwarp; r < D_H; r += 512) {
        const float* row = W + (size_t)r * D_IN;
        float acc = 0.0f;
        for (int j = lane; j < D_IN; j += 32) acc = fmaf(row[j], t[j], acc);
#pragma unroll
        for (int o = 16; o > 0; o >>= 1) acc += __shfl_xor_sync(0xffffffffu, acc, o);
        if (lane == 0) s[r] = acc * invn;
    }
    __threadfence();
    if (tid == 0) lastf = (atomicAdd(&g_ticket, 1) == (int)gridDim.x - 1);
    __syncthreads();
    if (lastf) {
        __threadfence();
        float q = 0.0f;
        for (int i = tid; i < D_H; i += 256) { float v = s[i]; q = fmaf(v, v, q); }
#pragma unroll
        for (int o = 16; o > 0; o >>= 1) q += __shfl_xor_sync(0xffffffffu, q, o);
        if (lane == 0) shw[w] = q;
        __syncthreads();
        if (tid == 0) {
            float Q = 0.0f;
#pragma unroll
            for (int i = 0; i < 8; i++) Q += shw[i];
            scal[1] = (sqrtf(Q) + EPSV) / Q;
        }
    }
}

// ================= bf16 3-pass aux GEMM =================
template <int AP>
__device__ __forceinline__ void prefetch_chunk(uint32_t sb_u, char* sb_p, int k0,
        const void* Ahi, const void* Alo,
        const __nv_bfloat16* __restrict__ Bhi, const __nv_bfloat16* __restrict__ Blo,
        int K, int NB, int m0, int n0) {
    const int t = threadIdx.x;
#pragma unroll
    for (int r = 0; r < 4; r++) {
        const int idx = t + (r << 7);
        const int row = idx >> 3;
        const int c   = idx & 7;
        const uint32_t soff = (uint32_t)row * ROW_B + (c << 4);
        const void *pa, *pl;
        if (AP == 0) {
            const size_t ga = (size_t)(m0 + row) * K + k0 + (c << 3);
            pa = (const __nv_bfloat16*)Ahi + ga;
            pl = (const __nv_bfloat16*)Alo + ga;
        } else {
            const size_t gb = ((size_t)((m0 >> 6) * NKCH + (k0 >> 7))) * STILE +
                              (size_t)row * SROW + ((k0 & 127) << 1) + (c << 4);
            pa = (const char*)Ahi + gb;
            pl = (const char*)Alo + gb;
        }
        CP16(sb_u + TILE_A_HI + soff, pa);
        CP16(sb_u + TILE_A_LO + soff, pl);
        const int gn = n0 + row;
        if (gn < NB) {
            const size_t gb2 = (size_t)gn * K + k0 + (c << 3);
            CP16(sb_u + TILE_B_HI + soff, Bhi + gb2);
            CP16(sb_u + TILE_B_LO + soff, Blo + gb2);
        } else {
            const uint4 z = make_uint4(0, 0, 0, 0);
            *reinterpret_cast<uint4*>(sb_p + TILE_B_HI + soff) = z;
            *reinterpret_cast<uint4*>(sb_p + TILE_B_LO + soff) = z;
        }
    }
}

template <int MODE, int AP>
__global__ void __launch_bounds__(128)
gemm_mma(const void* Ahi, const void* Alo,
         const __nv_bfloat16* __restrict__ Bhi, const __nv_bfloat16* __restrict__ Blo,
         const float* __restrict__ bias, float* __restrict__ outF,
         const float* __restrict__ scale_ptr, int K, int NB, int ldOut,
         const float* __restrict__ lb0, const float* __restrict__ lb1,
         const float* __restrict__ lb2, float* __restrict__ xpb) {
    extern __shared__ char smem[];
    const uint32_t sbase = smem_u32(smem);
    const int tid  = threadIdx.x;
    const int lane = tid & 31;
    const int wid  = tid >> 5;
    const int m0 = blockIdx.y * 64;
    const int n0 = blockIdx.x * 64;
    const int wm = (wid >> 1) << 5;
    const int wn = (wid & 1) << 5;
    const int NC = K >> 6;

    const int arow  = (lane & 7) | (((lane >> 3) & 1) << 3);
    const int akoff = ((lane >> 4) & 1) << 3;
    const int brow  = (lane & 7) | (((lane >> 4) & 1) << 3);
    const int bkoff = ((lane >> 3) & 1) << 3;

    float acc[2][4][4] = {};

    prefetch_chunk<AP>(sbase, smem, 0, Ahi, Alo, Bhi, Blo, K, NB, m0, n0);
    CP_COMMIT();

    for (int c = 0; c < NC; c++) {
        if (c + 1 < NC) {
            const int ns = (c + 1) & 1;
            prefetch_chunk<AP>(sbase + ns * STAGE_BYTES, smem + ns * STAGE_BYTES,
                               (c + 1) << 6, Ahi, Alo, Bhi, Blo, K, NB, m0, n0);
            CP_COMMIT();
            CP_WAIT(1);
        } else {
            CP_WAIT(0);
        }
        __syncthreads();

        const uint32_t st = sbase + (c & 1) * STAGE_BYTES;
#pragma unroll
        for (int kk = 0; kk < 4; kk++) {
            const int k0 = kk << 4;
            uint32_t ah[2][4], al[2][4], bh[2][4], bl[2][4];
#pragma unroll
            for (int a = 0; a < 2; a++) {
                const uint32_t off = (uint32_t)(wm + (a << 4) + arow) * ROW_B +
                                     ((k0 + akoff) << 1);
                ldsm4(ah[a], st + TILE_A_HI + off);
                ldsm4(al[a], st + TILE_A_LO + off);
            }
#pragma unroll
            for (int b = 0; b < 2; b++) {
                const uint32_t off = (uint32_t)(wn + (b << 4) + brow) * ROW_B +
                                     ((k0 + bkoff) << 1);
                ldsm4(bh[b], st + TILE_B_HI + off);
                ldsm4(bl[b], st + TILE_B_LO + off);
            }
#pragma unroll
            for (int a = 0; a < 2; a++)
#pragma unroll
                for (int j = 0; j < 4; j++)
                    mma_bf16(acc[a][j], ah[a], &bh[j >> 1][(j & 1) << 1]);
#pragma unroll
            for (int a = 0; a < 2; a++)
#pragma unroll
                for (int j = 0; j < 4; j++)
                    mma_bf16(acc[a][j], ah[a], &bl[j >> 1][(j & 1) << 1]);
#pragma unroll
            for (int a = 0; a < 2; a++)
#pragma unroll
                for (int j = 0; j < 4; j++)
                    mma_bf16(acc[a][j], al[a], &bh[j >> 1][(j & 1) << 1]);
        }
        __syncthreads();
    }

    const float scale = (MODE == 0) ? *scale_ptr : 1.0f;
    const int g  = lane >> 2;
    const int i2 = (lane & 3) << 1;
#pragma unroll
    for (int a = 0; a < 2; a++)
#pragma unroll
        for (int j = 0; j < 4; j++)
#pragma unroll
            for (int e = 0; e < 4; e++) {
                const int m = m0 + wm + (a << 4) + g + ((e >> 1) << 3);
                const int n = n0 + wn + (j << 3) + i2 + (e & 1);
                const float r = acc[a][j][e];
                if (MODE == 0) {
                    const float v = fmaf(r, scale, bias[n]);
                    const size_t idx = (size_t)m * D_H + n;
                    xpb[idx] = v + lb0[n];
                    xpb[(size_t)BATCH * D_H + idx] = v + lb1[n];
                    xpb[(size_t)2 * BATCH * D_H + idx] = v + lb2[n];
                } else {
                    if (n < NB) outF[(size_t)m * ldOut + n] = r + bias[n];
                }
            }
}

// ================= step GEMM: 4 warps, 32x32 warp tiles, bulk panels =============
__device__ __forceinline__ void issue_chunk(uint32_t st_u, uint32_t mbar, int chunk,
        const char* __restrict__ AH, const char* __restrict__ AL,
        const char* __restrict__ BH, const char* __restrict__ BL, int mt, int nt) {
    const size_t ab = ((size_t)(mt * NKCH + chunk)) * STILE;
    const size_t bb = ((size_t)(nt * NKCH + chunk)) * STILE;
    BULKT(st_u + S_AH, AH + ab, mbar);
    BULKT(st_u + S_AL, AL + ab, mbar);
    BULKT(st_u + S_BH, BH + bb, mbar);
    BULKT(st_u + S_BL, BL + bb, mbar);
}

__global__ void __launch_bounds__(128)
gemm_step(const char* __restrict__ AH, const char* __restrict__ AL,
          const char* __restrict__ BH, const char* __restrict__ BL,
          const float* __restrict__ xpb, const float* __restrict__ hold,
          float* __restrict__ outF,
          char* __restrict__ outHp, char* __restrict__ outLp) {
    extern __shared__ char smem[];
    const uint32_t sbase = smem_u32(smem);
    const uint32_t data0 = sbase + S_DATA;
    const int tid  = threadIdx.x;
    const int lane = tid & 31;
    const int wid  = tid >> 5;
    const int mt = blockIdx.y;        // 0..3
    const int nt = blockIdx.x;        // 0..31
    const int m0 = mt << 6;
    const int n0 = nt << 6;
    const int wm = (wid >> 1) << 5;   // 0 or 32
    const int wn = (wid & 1) << 5;    // 0 or 32
    const int NC = NKCH;              // 16 chunks of 128

    const int arow  = (lane & 7) | (((lane >> 3) & 1) << 3);
    const int akoff = ((lane >> 4) & 1) << 3;
    const int brow  = (lane & 7) | (((lane >> 4) & 1) << 3);
    const int bkoff = ((lane >> 3) & 1) << 3;

    float accm[2][4][4] = {};   // ah*bh
    float acc1[2][4][4] = {};   // ah*bl
    float acc2[2][4][4] = {};   // al*bh

    if (tid == 0) {
        MBAR_INIT(sbase + 0, 1);
        MBAR_INIT(sbase + 16, 1);
        MBAR_INIT(sbase + 32, 1);
    }
    __syncthreads();
    if (tid == 0) {
        MBAR_EXPECT(sbase + 0, S_TX);
        issue_chunk(data0, sbase + 0, 0, AH, AL, BH, BL, mt, nt);
        MBAR_EXPECT(sbase + 16, S_TX);
        issue_chunk(data0 + S_STAGE, sbase + 16, 1, AH, AL, BH, BL, mt, nt);
    }

    int ph0 = 0, ph1 = 0, ph2 = 0;
    int s = 0;
    for (int c = 0; c < NC; c++) {
        if (c + 2 < NC) {
            __syncthreads();   // everyone finished reading the stage being reused
            if (tid == 0) {
                const int s2 = (s + 2 >= 3) ? (s - 1) : (s + 2);
                MBAR_EXPECT(sbase + (s2 << 4), S_TX);
                issue_chunk(data0 + s2 * S_STAGE, sbase + (s2 << 4), c + 2,
                            AH, AL, BH, BL, mt, nt);
            }
        }
        if (s == 0)      { MBAR_WAIT(sbase + 0,  ph0); ph0 ^= 1; }
        else if (s == 1) { MBAR_WAIT(sbase + 16, ph1); ph1 ^= 1; }
        else             { MBAR_WAIT(sbase + 32, ph2); ph2 ^= 1; }

        const uint32_t st = data0 + s * S_STAGE;
#pragma unroll
        for (int kk = 0; kk < 8; kk++) {
            const int k0 = kk << 4;
            uint32_t ah[2][4], al[2][4], bh[2][4], bl[2][4];
#pragma unroll
            for (int a = 0; a < 2; a++) {
                const uint32_t off = (uint32_t)(wm + (a << 4) + arow) * SROW +
                                     ((k0 + akoff) << 1);
                ldsm4(ah[a], st + S_AH + off);
                ldsm4(al[a], st + S_AL + off);
            }
#pragma unroll
            for (int b = 0; b < 2; b++) {
                const uint32_t off = (uint32_t)(wn + (b << 4) + brow) * SROW +
                                     ((k0 + bkoff) << 1);
                ldsm4(bh[b], st + S_BH + off);
                ldsm4(bl[b], st + S_BL + off);
            }
#pragma unroll
            for (int a = 0; a < 2; a++)
#pragma unroll
                for (int j = 0; j < 4; j++) {
                    mma_bf16(accm[a][j], ah[a], &bh[j >> 1][(j & 1) << 1]);
                    mma_bf16(acc1[a][j], ah[a], &bl[j >> 1][(j & 1) << 1]);
                    mma_bf16(acc2[a][j], al[a], &bh[j >> 1][(j & 1) << 1]);
                }
        }
        s = (s + 1 >= 3) ? 0 : (s + 1);
    }

    // epilogue: fp32 h (plain) + bf16 hi/lo limbs (packed panel layout)
    const int g  = lane >> 2;
    const int i2 = (lane & 3) << 1;
#pragma unroll
    for (int a = 0; a < 2; a++)
#pragma unroll
        for (int j = 0; j < 4; j++)
#pragma unroll
            for (int eh = 0; eh < 2; eh++) {
                const int m = m0 + wm + (a << 4) + g + (eh << 3);
                const int n = n0 + wn + (j << 3) + i2;
                const size_t idx = (size_t)m * D_H + n;
                const float r0 = accm[a][j][eh * 2 + 0] + acc1[a][j][eh * 2 + 0] +
                                 acc2[a][j][eh * 2 + 0];
                const float r1 = accm[a][j][eh * 2 + 1] + acc1[a][j][eh * 2 + 1] +
                                 acc2[a][j][eh * 2 + 1];
                const float2 xb = *reinterpret_cast<const float2*>(xpb + idx);
                const float2 ho = *reinterpret_cast<const float2*>(hold + idx);
                const float hn0 = 0.5f * ho.x + 0.5f * tanhf(xb.x + r0);
                const float hn1 = 0.5f * ho.y + 0.5f * tanhf(xb.y + r1);
                *reinterpret_cast<float2*>(outF + idx) = make_float2(hn0, hn1);
                const __nv_bfloat16 b0 = __float2bfloat16(hn0);
                const __nv_bfloat16 b1 = __float2bfloat16(hn1);
                __nv_bfloat162 hiv, lov;
                hiv.x = b0; hiv.y = b1;
                lov.x = __float2bfloat16(hn0 - __bfloat162float(b0));
                lov.y = __float2bfloat16(hn1 - __bfloat162float(b1));
                const size_t pidx = pkoff(m, n);
                *reinterpret_cast<__nv_bfloat162*>(outHp + pidx) = hiv;
                *reinterpret_cast<__nv_bfloat162*>(outLp + pidx) = lov;
            }
}

// ---------------- host ----------------
extern "C" void kernel_launch(void* const* d_in, const int* in_sizes, int n_in,
                              void* d_out, int out_size) {
    const float* x     = (const float*)d_in[0];
    const float* Winw  = (const float*)d_in[1];
    const float* Winb  = (const float*)d_in[2];
    const float* u     = (const float*)d_in[3];
    const float* W0    = (const float*)d_in[4];
    const float* b0    = (const float*)d_in[5];
    const float* W1    = (const float*)d_in[6];
    const float* b1    = (const float*)d_in[7];
    const float* W2    = (const float*)d_in[8];
    const float* b2    = (const float*)d_in[9];
    const float* headw = (const float*)d_in[10];
    const float* headb = (const float*)d_in[11];
    float* out = (float*)d_out;

    float *t, *s, *scal, *hA, *hB, *xpb;
    cudaGetSymbolAddress((void**)&t, g_t);
    cudaGetSymbolAddress((void**)&s, g_s);
    cudaGetSymbolAddress((void**)&scal, g_scal);
    cudaGetSymbolAddress((void**)&xpb, g_xpb);
    cudaGetSymbolAddress((void**)&hA, g_hA);
    cudaGetSymbolAddress((void**)&hB, g_hB);
    char *W0hp, *W0lp, *W1hp, *W1lp, *W2hp, *W2lp, *hPhA, *hPlA, *hPhB, *hPlB;
    cudaGetSymbolAddress((void**)&W0hp, g_W0hp); cudaGetSymbolAddress((void**)&W0lp, g_W0lp);
    cudaGetSymbolAddress((void**)&W1hp, g_W1hp); cudaGetSymbolAddress((void**)&W1lp, g_W1lp);
    cudaGetSymbolAddress((void**)&W2hp, g_W2hp); cudaGetSymbolAddress((void**)&W2lp, g_W2lp);
    cudaGetSymbolAddress((void**)&hPhA, g_hPhA); cudaGetSymbolAddress((void**)&hPlA, g_hPlA);
    cudaGetSymbolAddress((void**)&hPhB, g_hPhB); cudaGetSymbolAddress((void**)&hPlB, g_hPlB);
    __nv_bfloat16 *Winh, *Winl, *Hdh, *Hdl, *xh, *xl;
    cudaGetSymbolAddress((void**)&Winh, g_Winhi); cudaGetSymbolAddress((void**)&Winl, g_Winlo);
    cudaGetSymbolAddress((void**)&Hdh, g_Hdhi);   cudaGetSymbolAddress((void**)&Hdl, g_Hdlo);
    cudaGetSymbolAddress((void**)&xh, g_xhi);     cudaGetSymbolAddress((void**)&xl, g_xlo);

    cudaFuncSetAttribute(gemm_mma<0, 0>, cudaFuncAttributeMaxDynamicSharedMemorySize, SMEM_BYTES);
    cudaFuncSetAttribute(gemm_mma<2, 1>, cudaFuncAttributeMaxDynamicSharedMemorySize, SMEM_BYTES);
    cudaFuncSetAttribute(gemm_step, cudaFuncAttributeMaxDynamicSharedMemorySize, S_SMEM);

    // 0: prep (splits + packing + zeros + matvec_t + ticket reset)
    prep_kernel<<<592, 256>>>(W0, W1, W2, Winw, headw, x, u);
    // 1: sigma (matvec_s + reduce, ticket-synced)
    sigma_kernel<<<64, 256>>>(Winw, t, s, scal);
    // 2: x_proj (writes xpb[0..2] with per-layer bias folded)
    {
        dim3 grid(D_H / 64, BATCH / 64);
        gemm_mma<0, 0><<<grid, 128, SMEM_BYTES>>>(xh, xl, Winh, Winl, Winb,
                                                  nullptr, scal + 1, D_IN, D_H, D_H,
                                                  b0, b1, b2, xpb);
    }
    // 3..92: 30 steps x 3 layers
    const char* Whp[3] = {W0hp, W1hp, W2hp};
    const char* Wlp[3] = {W0lp, W1lp, W2lp};
    float *cur = hA, *nxt = hB;
    char *curh = hPhA, *curl = hPlA, *nxth = hPhB, *nxtl = hPlB;
    dim3 gstep(D_H / 64, BATCH / 64);
    for (int st = 0; st < STEPS; st++) {
        for (int l = 0; l < 3; l++) {
            gemm_step<<<gstep, 128, S_SMEM>>>(curh, curl, Whp[l], Wlp[l],
                                              xpb + (size_t)l * BATCH * D_H,
                                              cur, nxt, nxth, nxtl);
            float* tf = cur; cur = nxt; nxt = tf;
            char* th = curh; curh = nxth; nxth = th;
            char* tl = curl; curl = nxtl; nxtl = tl;
        }
    }
    // 93: head (A = packed final h)
    {
        dim3 grid((D_OUT + 63) / 64, BATCH / 64);
        gemm_mma<2, 1><<<grid, 128, SMEM_BYTES>>>(curh, curl, Hdh, Hdl, headb,
                                                  out, nullptr, D_H, D_OUT, D_OUT,
                                                  nullptr, nullptr, nullptr, nullptr);
    }
}

// round 12
// speedup vs baseline: 1.5884x; 1.0664x over previous
#include <cuda_runtime.h>
#include <cuda_bf16.h>
#include <math.h>
#include <stdint.h>

#define D_IN   1024
#define D_H    2048
#define BATCH  256
#define D_OUT  1000
#define EPSV   1e-12f
#define STEPS  30

// ---- bf16 aux GEMM smem geometry (x_proj / head, 128-thread kernel) ----
#define ROW_B      144
#define TILE_A_HI  0
#define TILE_A_LO  9216
#define TILE_B_HI  18432
#define TILE_B_LO  27648
#define STAGE_BYTES 36864
#define SMEM_BYTES  (2 * STAGE_BYTES)

// ---- step GEMM smem: BK=128 panels, 4 tiles of 64 rows x 272B, 3 stages ----
#define SROW     272
#define STILE    17408                // 64 * 272
#define S_AH     0
#define S_AL     17408
#define S_BH     34816
#define S_BL     52224
#define S_STAGE  69632
#define S_DATA   128                  // mbarriers below
#define S_SMEM   (S_DATA + 3 * S_STAGE)   // 209024
#define S_TX     69632                // bytes per stage

// panel block byte offset for element (row-dim r, k-dim k) of a [.., 2048] matrix
#define NKCH     16                   // k chunks per 2048
__host__ __device__ __forceinline__ size_t pkoff(int r, int k) {
    return ((size_t)((r >> 6) * NKCH + (k >> 7))) * STILE +
           (size_t)(r & 63) * SROW + (size_t)((k & 127) << 1);
}

// ---------------- device scratch (no allocations allowed) ----------------
__device__ float g_t[D_IN];
__device__ float g_s[D_H];
__device__ float g_scal[4];              // [1] = 1/sigma
__device__ int   g_ticket;
__device__ float g_xpb[3][BATCH * D_H];  // xproj + bias_l
__device__ float g_hA[BATCH * D_H];
__device__ float g_hB[BATCH * D_H];

// packed (panel-layout) step operands
#define WPK_BYTES ((size_t)32 * NKCH * STILE)   // 8,912,896
#define HPK_BYTES ((size_t)4  * NKCH * STILE)   // 1,114,112
__device__ char g_W0hp[WPK_BYTES], g_W0lp[WPK_BYTES];
__device__ char g_W1hp[WPK_BYTES], g_W1lp[WPK_BYTES];
__device__ char g_W2hp[WPK_BYTES], g_W2lp[WPK_BYTES];
__device__ char g_hPhA[HPK_BYTES], g_hPlA[HPK_BYTES];
__device__ char g_hPhB[HPK_BYTES], g_hPlB[HPK_BYTES];

// plain bf16 splits (x_proj / head B operands)
__device__ __nv_bfloat16 g_Winhi[D_H * D_IN], g_Winlo[D_H * D_IN];
__device__ __nv_bfloat16 g_Hdhi[D_OUT * D_H], g_Hdlo[D_OUT * D_H];
__device__ __nv_bfloat16 g_xhi[BATCH * D_IN], g_xlo[BATCH * D_IN];

// ---------------- portable PTX helpers ----------------
__device__ __forceinline__ uint32_t smem_u32(const void* p) {
    uint32_t a;
    asm("{ .reg .u64 t; cvta.to.shared.u64 t, %1; cvt.u32.u64 %0, t; }" : "=r"(a) : "l"(p));
    return a;
}
#define CP16(dst, src) asm volatile("cp.async.cg.shared.global [%0], [%1], 16;" :: "r"(dst), "l"(src))
#define CP_COMMIT()    asm volatile("cp.async.commit_group;" ::: "memory")
#define CP_WAIT(n)     asm volatile("cp.async.wait_group %0;" :: "n"(n) : "memory")

#define MBAR_INIT(a, c) asm volatile("mbarrier.init.shared.b64 [%0], %1;" :: "r"(a), "r"(c) : "memory")
#define MBAR_EXPECT(a, bytes) \
    asm volatile("mbarrier.arrive.expect_tx.shared.b64 _, [%0], %1;" :: "r"(a), "r"(bytes) : "memory")
#define BULKT(dst, src, mbar) \
    asm volatile("cp.async.bulk.shared::cluster.global.mbarrier::complete_tx::bytes [%0], [%1], 17408, [%2];" \
        :: "r"(dst), "l"(src), "r"(mbar) : "memory")
#define MBAR_WAIT(mbar, parity) do {                                              \
    uint32_t _m = (mbar), _p = (parity), _d;                                      \
    asm volatile("{ .reg .pred p; mbarrier.try_wait.parity.acquire.cta.shared::cta.b64 p, [%1], %2; selp.b32 %0, 1, 0, p; }" \
        : "=r"(_d) : "r"(_m), "r"(_p) : "memory");                                \
    if (!_d) {                                                                    \
        asm volatile("{ .reg .pred P1; WL_%=: mbarrier.try_wait.parity.acquire.cta.shared::cta.b64 P1, [%0], %1, 0x989680; @P1 bra.uni WD_%=; bra.uni WL_%=; WD_%=: }" \
            :: "r"(_m), "r"(_p) : "memory");                                      \
    }                                                                             \
} while (0)

__device__ __forceinline__ void ldsm4(uint32_t* r, uint32_t addr) {
    asm volatile("ldmatrix.sync.aligned.m8n8.x4.shared.b16 {%0,%1,%2,%3}, [%4];"
        : "=r"(r[0]), "=r"(r[1]), "=r"(r[2]), "=r"(r[3]) : "r"(addr));
}
__device__ __forceinline__ void mma_bf16(float* c, const uint32_t* a, const uint32_t* b) {
    asm volatile("mma.sync.aligned.m16n8k16.row.col.f32.bf16.bf16.f32 "
        "{%0,%1,%2,%3}, {%4,%5,%6,%7}, {%8,%9}, {%0,%1,%2,%3};"
        : "+f"(c[0]), "+f"(c[1]), "+f"(c[2]), "+f"(c[3])
        : "r"(a[0]), "r"(a[1]), "r"(a[2]), "r"(a[3]), "r"(b[0]), "r"(b[1]));
}

// ---------------- prep: splits + packing + h0 zeros + matvec_t + ticket reset ----
__device__ __forceinline__ void split_plain(const float* __restrict__ src,
        __nv_bfloat16* __restrict__ hi, __nv_bfloat16* __restrict__ lo, int i) {
    float a = src[i];
    __nv_bfloat16 h = __float2bfloat16(a);
    hi[i] = h;
    lo[i] = __float2bfloat16(a - __bfloat162float(h));
}
__device__ __forceinline__ void split_pack(const float* __restrict__ src,
        char* __restrict__ hp, char* __restrict__ lp, int i) {
    const int r = i >> 11, k = i & 2047;
    const size_t off = pkoff(r, k);
    float a = src[i];
    __nv_bfloat16 h = __float2bfloat16(a);
    *reinterpret_cast<__nv_bfloat16*>(hp + off) = h;
    *reinterpret_cast<__nv_bfloat16*>(lp + off) =
        __float2bfloat16(a - __bfloat162float(h));
}

__global__ void prep_kernel(const float* __restrict__ W0, const float* __restrict__ W1,
                            const float* __restrict__ W2, const float* __restrict__ Win,
                            const float* __restrict__ Hd, const float* __restrict__ x,
                            const float* __restrict__ u) {
    const int stride = gridDim.x * blockDim.x;
    const int t0 = blockIdx.x * blockDim.x + threadIdx.x;
    if (t0 == 0) g_ticket = 0;
    for (int i = t0; i < D_H * D_H; i += stride) {
        split_pack(W0, g_W0hp, g_W0lp, i);
        split_pack(W1, g_W1hp, g_W1lp, i);
        split_pack(W2, g_W2hp, g_W2lp, i);
    }
    for (int i = t0; i < D_H * D_IN; i += stride) split_plain(Win, g_Winhi, g_Winlo, i);
    for (int i = t0; i < D_OUT * D_H; i += stride) split_plain(Hd, g_Hdhi, g_Hdlo, i);
    for (int i = t0; i < BATCH * D_IN; i += stride) split_plain(x, g_xhi, g_xlo, i);
    for (int i = t0; i < BATCH * D_H; i += stride) g_hA[i] = 0.0f;
    for (int i = t0; i < (int)(HPK_BYTES / 4); i += stride) {
        reinterpret_cast<uint32_t*>(g_hPhA)[i] = 0u;
        reinterpret_cast<uint32_t*>(g_hPlA)[i] = 0u;
    }
    for (int j = t0; j < D_IN; j += stride) {
        float acc = 0.0f;
#pragma unroll 4
        for (int i = 0; i < D_H; i++) acc = fmaf(Win[(size_t)i * D_IN + j], u[i], acc);
        g_t[j] = acc;
    }
}

// ---------------- sigma: matvec_s + final reduce, ticket-synced ----------------
__global__ void sigma_kernel(const float* __restrict__ W, const float* __restrict__ t,
                             float* __restrict__ s, float* __restrict__ scal) {
    __shared__ float shw[8];
    __shared__ int lastf;
    const int tid = threadIdx.x;
    const int lane = tid & 31;
    const int w = tid >> 5;
    float ss = 0.0f;
#pragma unroll
    for (int i = 0; i < 4; i++) {
        float v = t[tid + (i << 8)];
        ss = fmaf(v, v, ss);
    }
#pragma unroll
    for (int o = 16; o > 0; o >>= 1) ss += __shfl_xor_sync(0xffffffffu, ss, o);
    if (lane == 0) shw[w] = ss;
    __syncthreads();
    float tot = shw[lane & 7];
#pragma unroll
    for (int o = 4; o > 0; o >>= 1) tot += __shfl_xor_sync(0xffffffffu, tot, o);
    const float invn = 1.0f / (sqrtf(tot) + EPSV);

    const int gwarp = blockIdx.x * 8 + w;
    for (int r = gwarp; r < D_H; r += 512) {
        const float* row = W + (size_t)r * D_IN;
        float acc = 0.0f;
        for (int j = lane; j < D_IN; j += 32) acc = fmaf(row[j], t[j], acc);
#pragma unroll
        for (int o = 16; o > 0; o >>= 1) acc += __shfl_xor_sync(0xffffffffu, acc, o);
        if (lane == 0) s[r] = acc * invn;
    }
    __threadfence();
    if (tid == 0) lastf = (atomicAdd(&g_ticket, 1) == (int)gridDim.x - 1);
    __syncthreads();
    if (lastf) {
        __threadfence();
        float q = 0.0f;
        for (int i = tid; i < D_H; i += 256) { float v = s[i]; q = fmaf(v, v, q); }
#pragma unroll
        for (int o = 16; o > 0; o >>= 1) q += __shfl_xor_sync(0xffffffffu, q, o);
        if (lane == 0) shw[w] = q;
        __syncthreads();
        if (tid == 0) {
            float Q = 0.0f;
#pragma unroll
            for (int i = 0; i < 8; i++) Q += shw[i];
            scal[1] = (sqrtf(Q) + EPSV) / Q;
        }
    }
}

// ================= bf16 3-pass aux GEMM =================
template <int AP>
__device__ __forceinline__ void prefetch_chunk(uint32_t sb_u, char* sb_p, int k0,
        const void* Ahi, const void* Alo,
        const __nv_bfloat16* __restrict__ Bhi, const __nv_bfloat16* __restrict__ Blo,
        int K, int NB, int m0, int n0) {
    const int t = threadIdx.x;
#pragma unroll
    for (int r = 0; r < 4; r++) {
        const int idx = t + (r << 7);
        const int row = idx >> 3;
        const int c   = idx & 7;
        const uint32_t soff = (uint32_t)row * ROW_B + (c << 4);
        const void *pa, *pl;
        if (AP == 0) {
            const size_t ga = (size_t)(m0 + row) * K + k0 + (c << 3);
            pa = (const __nv_bfloat16*)Ahi + ga;
            pl = (const __nv_bfloat16*)Alo + ga;
        } else {
            const size_t gb = ((size_t)((m0 >> 6) * NKCH + (k0 >> 7))) * STILE +
                              (size_t)row * SROW + ((k0 & 127) << 1) + (c << 4);
            pa = (const char*)Ahi + gb;
            pl = (const char*)Alo + gb;
        }
        CP16(sb_u + TILE_A_HI + soff, pa);
        CP16(sb_u + TILE_A_LO + soff, pl);
        const int gn = n0 + row;
        if (gn < NB) {
            const size_t gb2 = (size_t)gn * K + k0 + (c << 3);
            CP16(sb_u + TILE_B_HI + soff, Bhi + gb2);
            CP16(sb_u + TILE_B_LO + soff, Blo + gb2);
        } else {
            const uint4 z = make_uint4(0, 0, 0, 0);
            *reinterpret_cast<uint4*>(sb_p + TILE_B_HI + soff) = z;
            *reinterpret_cast<uint4*>(sb_p + TILE_B_LO + soff) = z;
        }
    }
}

template <int MODE, int AP>
__global__ void __launch_bounds__(128)
gemm_mma(const void* Ahi, const void* Alo,
         const __nv_bfloat16* __restrict__ Bhi, const __nv_bfloat16* __restrict__ Blo,
         const float* __restrict__ bias, float* __restrict__ outF,
         const float* __restrict__ scale_ptr, int K, int NB, int ldOut,
         const float* __restrict__ lb0, const float* __restrict__ lb1,
         const float* __restrict__ lb2, float* __restrict__ xpb) {
    extern __shared__ char smem[];
    const uint32_t sbase = smem_u32(smem);
    const int tid  = threadIdx.x;
    const int lane = tid & 31;
    const int wid  = tid >> 5;
    const int m0 = blockIdx.y * 64;
    const int n0 = blockIdx.x * 64;
    const int wm = (wid >> 1) << 5;
    const int wn = (wid & 1) << 5;
    const int NC = K >> 6;

    const int arow  = (lane & 7) | (((lane >> 3) & 1) << 3);
    const int akoff = ((lane >> 4) & 1) << 3;
    const int brow  = (lane & 7) | (((lane >> 4) & 1) << 3);
    const int bkoff = ((lane >> 3) & 1) << 3;

    float acc[2][4][4] = {};

    prefetch_chunk<AP>(sbase, smem, 0, Ahi, Alo, Bhi, Blo, K, NB, m0, n0);
    CP_COMMIT();

    for (int c = 0; c < NC; c++) {
        if (c + 1 < NC) {
            const int ns = (c + 1) & 1;
            prefetch_chunk<AP>(sbase + ns * STAGE_BYTES, smem + ns * STAGE_BYTES,
                               (c + 1) << 6, Ahi, Alo, Bhi, Blo, K, NB, m0, n0);
            CP_COMMIT();
            CP_WAIT(1);
        } else {
            CP_WAIT(0);
        }
        __syncthreads();

        const uint32_t st = sbase + (c & 1) * STAGE_BYTES;
#pragma unroll
        for (int kk = 0; kk < 4; kk++) {
            const int k0 = kk << 4;
            uint32_t ah[2][4], al[2][4], bh[2][4], bl[2][4];
#pragma unroll
            for (int a = 0; a < 2; a++) {
                const uint32_t off = (uint32_t)(wm + (a << 4) + arow) * ROW_B +
                                     ((k0 + akoff) << 1);
                ldsm4(ah[a], st + TILE_A_HI + off);
                ldsm4(al[a], st + TILE_A_LO + off);
            }
#pragma unroll
            for (int b = 0; b < 2; b++) {
                const uint32_t off = (uint32_t)(wn + (b << 4) + brow) * ROW_B +
                                     ((k0 + bkoff) << 1);
                ldsm4(bh[b], st + TILE_B_HI + off);
                ldsm4(bl[b], st + TILE_B_LO + off);
            }
#pragma unroll
            for (int a = 0; a < 2; a++)
#pragma unroll
                for (int j = 0; j < 4; j++)
                    mma_bf16(acc[a][j], ah[a], &bh[j >> 1][(j & 1) << 1]);
#pragma unroll
            for (int a = 0; a < 2; a++)
#pragma unroll
                for (int j = 0; j < 4; j++)
                    mma_bf16(acc[a][j], ah[a], &bl[j >> 1][(j & 1) << 1]);
#pragma unroll
            for (int a = 0; a < 2; a++)
#pragma unroll
                for (int j = 0; j < 4; j++)
                    mma_bf16(acc[a][j], al[a], &bh[j >> 1][(j & 1) << 1]);
        }
        __syncthreads();
    }

    const float scale = (MODE == 0) ? *scale_ptr : 1.0f;
    const int g  = lane >> 2;
    const int i2 = (lane & 3) << 1;
#pragma unroll
    for (int a = 0; a < 2; a++)
#pragma unroll
        for (int j = 0; j < 4; j++)
#pragma unroll
            for (int e = 0; e < 4; e++) {
                const int m = m0 + wm + (a << 4) + g + ((e >> 1) << 3);
                const int n = n0 + wn + (j << 3) + i2 + (e & 1);
                const float r = acc[a][j][e];
                if (MODE == 0) {
                    const float v = fmaf(r, scale, bias[n]);
                    const size_t idx = (size_t)m * D_H + n;
                    xpb[idx] = v + lb0[n];
                    xpb[(size_t)BATCH * D_H + idx] = v + lb1[n];
                    xpb[(size_t)2 * BATCH * D_H + idx] = v + lb2[n];
                } else {
                    if (n < NB) outF[(size_t)m * ldOut + n] = r + bias[n];
                }
            }
}

// ================= step GEMM: 8 warps, warp-split-K, 32x32 warp tiles =============
// Warp pairs (wk=0/1) share a 32x32 output tile; each covers half of every
// BK=128 chunk (kk 0-3 vs 4-7). Final cross-warp sum via smem (stage region).
__device__ __forceinline__ void issue_chunk(uint32_t st_u, uint32_t mbar, int chunk,
        const char* __restrict__ AH, const char* __restrict__ AL,
        const char* __restrict__ BH, const char* __restrict__ BL, int mt, int nt) {
    const size_t ab = ((size_t)(mt * NKCH + chunk)) * STILE;
    const size_t bb = ((size_t)(nt * NKCH + chunk)) * STILE;
    BULKT(st_u + S_AH, AH + ab, mbar);
    BULKT(st_u + S_AL, AL + ab, mbar);
    BULKT(st_u + S_BH, BH + bb, mbar);
    BULKT(st_u + S_BL, BL + bb, mbar);
}

__global__ void __launch_bounds__(256)
gemm_step(const char* __restrict__ AH, const char* __restrict__ AL,
          const char* __restrict__ BH, const char* __restrict__ BL,
          const float* __restrict__ xpb, const float* __restrict__ hold,
          float* __restrict__ outF,
          char* __restrict__ outHp, char* __restrict__ outLp) {
    extern __shared__ char smem[];
    const uint32_t sbase = smem_u32(smem);
    const uint32_t data0 = sbase + S_DATA;
    const int tid  = threadIdx.x;
    const int lane = tid & 31;
    const int wid  = tid >> 5;
    const int wk   = wid & 1;         // k half
    const int wq   = wid >> 1;        // 0..3 output warp-tile
    const int mt = blockIdx.y;        // 0..3
    const int nt = blockIdx.x;        // 0..31
    const int m0 = mt << 6;
    const int n0 = nt << 6;
    const int wm = (wq >> 1) << 5;
    const int wn = (wq & 1) << 5;
    const int NC = NKCH;              // 16 chunks of 128

    const int arow  = (lane & 7) | (((lane >> 3) & 1) << 3);
    const int akoff = ((lane >> 4) & 1) << 3;
    const int brow  = (lane & 7) | (((lane >> 4) & 1) << 3);
    const int bkoff = ((lane >> 3) & 1) << 3;
    const int kbase = wk << 2;        // kk 0-3 or 4-7

    float accm[2][4][4] = {};
    float acc1[2][4][4] = {};
    float acc2[2][4][4] = {};

    if (tid == 0) {
        MBAR_INIT(sbase + 0, 1);
        MBAR_INIT(sbase + 16, 1);
        MBAR_INIT(sbase + 32, 1);
    }
    __syncthreads();
    if (tid == 0) {
        MBAR_EXPECT(sbase + 0, S_TX);
        issue_chunk(data0, sbase + 0, 0, AH, AL, BH, BL, mt, nt);
        MBAR_EXPECT(sbase + 16, S_TX);
        issue_chunk(data0 + S_STAGE, sbase + 16, 1, AH, AL, BH, BL, mt, nt);
    }

    int ph0 = 0, ph1 = 0, ph2 = 0;
    int s = 0;
    for (int c = 0; c < NC; c++) {
        if (c + 2 < NC) {
            __syncthreads();   // everyone finished reading the stage being reused
            if (tid == 0) {
                const int s2 = (s + 2 >= 3) ? (s - 1) : (s + 2);
                MBAR_EXPECT(sbase + (s2 << 4), S_TX);
                issue_chunk(data0 + s2 * S_STAGE, sbase + (s2 << 4), c + 2,
                            AH, AL, BH, BL, mt, nt);
            }
        }
        if (s == 0)      { MBAR_WAIT(sbase + 0,  ph0); ph0 ^= 1; }
        else if (s == 1) { MBAR_WAIT(sbase + 16, ph1); ph1 ^= 1; }
        else             { MBAR_WAIT(sbase + 32, ph2); ph2 ^= 1; }

        const uint32_t st = data0 + s * S_STAGE;
#pragma unroll
        for (int kki = 0; kki < 4; kki++) {
            const int k0 = (kbase + kki) << 4;
            uint32_t ah[2][4], al[2][4], bh[2][4], bl[2][4];
#pragma unroll
            for (int a = 0; a < 2; a++) {
                const uint32_t off = (uint32_t)(wm + (a << 4) + arow) * SROW +
                                     ((k0 + akoff) << 1);
                ldsm4(ah[a], st + S_AH + off);
                ldsm4(al[a], st + S_AL + off);
            }
#pragma unroll
            for (int b = 0; b < 2; b++) {
                const uint32_t off = (uint32_t)(wn + (b << 4) + brow) * SROW +
                                     ((k0 + bkoff) << 1);
                ldsm4(bh[b], st + S_BH + off);
                ldsm4(bl[b], st + S_BL + off);
            }
#pragma unroll
            for (int a = 0; a < 2; a++)
#pragma unroll
                for (int j = 0; j < 4; j++) {
                    mma_bf16(accm[a][j], ah[a], &bh[j >> 1][(j & 1) << 1]);
                    mma_bf16(acc1[a][j], ah[a], &bl[j >> 1][(j & 1) << 1]);
                    mma_bf16(acc2[a][j], al[a], &bh[j >> 1][(j & 1) << 1]);
                }
        }
        s = (s + 1 >= 3) ? 0 : (s + 1);
    }

    // reduce the 3 banks locally
    float rsum[2][4][4];
#pragma unroll
    for (int a = 0; a < 2; a++)
#pragma unroll
        for (int j = 0; j < 4; j++)
#pragma unroll
            for (int e = 0; e < 4; e++)
                rsum[a][j][e] = accm[a][j][e] + acc1[a][j][e] + acc2[a][j][e];

    // cross-warp k reduction via (now dead) stage smem: layout [wq][elem][lane]
    __syncthreads();
    float* red = reinterpret_cast<float*>(smem + S_DATA);
    if (wk == 1) {
        float* dst = red + (wq << 10);
#pragma unroll
        for (int a = 0; a < 2; a++)
#pragma unroll
            for (int j = 0; j < 4; j++)
#pragma unroll
                for (int e = 0; e < 4; e++)
                    dst[((a << 4) | (j << 2) | e) << 5 | lane] = rsum[a][j][e];
    }
    __syncthreads();
    if (wk == 0) {
        const float* src = red + (wq << 10);
#pragma unroll
        for (int a = 0; a < 2; a++)
#pragma unroll
            for (int j = 0; j < 4; j++)
#pragma unroll
                for (int e = 0; e < 4; e++)
                    rsum[a][j][e] += src[((a << 4) | (j << 2) | e) << 5 | lane];

        // epilogue: fp32 h (plain) + bf16 hi/lo limbs (packed panel layout)
        const int g  = lane >> 2;
        const int i2 = (lane & 3) << 1;
#pragma unroll
        for (int a = 0; a < 2; a++)
#pragma unroll
            for (int j = 0; j < 4; j++)
#pragma unroll
                for (int eh = 0; eh < 2; eh++) {
                    const int m = m0 + wm + (a << 4) + g + (eh << 3);
                    const int n = n0 + wn + (j << 3) + i2;
                    const size_t idx = (size_t)m * D_H + n;
                    const float r0 = rsum[a][j][eh * 2 + 0];
                    const float r1 = rsum[a][j][eh * 2 + 1];
                    const float2 xb = *reinterpret_cast<const float2*>(xpb + idx);
                    const float2 ho = *reinterpret_cast<const float2*>(hold + idx);
                    const float hn0 = 0.5f * ho.x + 0.5f * tanhf(xb.x + r0);
                    const float hn1 = 0.5f * ho.y + 0.5f * tanhf(xb.y + r1);
                    *reinterpret_cast<float2*>(outF + idx) = make_float2(hn0, hn1);
                    const __nv_bfloat16 b0 = __float2bfloat16(hn0);
                    const __nv_bfloat16 b1 = __float2bfloat16(hn1);
                    __nv_bfloat162 hiv, lov;
                    hiv.x = b0; hiv.y = b1;
                    lov.x = __float2bfloat16(hn0 - __bfloat162float(b0));
                    lov.y = __float2bfloat16(hn1 - __bfloat162float(b1));
                    const size_t pidx = pkoff(m, n);
                    *reinterpret_cast<__nv_bfloat162*>(outHp + pidx) = hiv;
                    *reinterpret_cast<__nv_bfloat162*>(outLp + pidx) = lov;
                }
    }
}

// ---------------- host ----------------
extern "C" void kernel_launch(void* const* d_in, const int* in_sizes, int n_in,
                              void* d_out, int out_size) {
    const float* x     = (const float*)d_in[0];
    const float* Winw  = (const float*)d_in[1];
    const float* Winb  = (const float*)d_in[2];
    const float* u     = (const float*)d_in[3];
    const float* W0    = (const float*)d_in[4];
    const float* b0    = (const float*)d_in[5];
    const float* W1    = (const float*)d_in[6];
    const float* b1    = (const float*)d_in[7];
    const float* W2    = (const float*)d_in[8];
    const float* b2    = (const float*)d_in[9];
    const float* headw = (const float*)d_in[10];
    const float* headb = (const float*)d_in[11];
    float* out = (float*)d_out;

    float *t, *s, *scal, *hA, *hB, *xpb;
    cudaGetSymbolAddress((void**)&t, g_t);
    cudaGetSymbolAddress((void**)&s, g_s);
    cudaGetSymbolAddress((void**)&scal, g_scal);
    cudaGetSymbolAddress((void**)&xpb, g_xpb);
    cudaGetSymbolAddress((void**)&hA, g_hA);
    cudaGetSymbolAddress((void**)&hB, g_hB);
    char *W0hp, *W0lp, *W1hp, *W1lp, *W2hp, *W2lp, *hPhA, *hPlA, *hPhB, *hPlB;
    cudaGetSymbolAddress((void**)&W0hp, g_W0hp); cudaGetSymbolAddress((void**)&W0lp, g_W0lp);
    cudaGetSymbolAddress((void**)&W1hp, g_W1hp); cudaGetSymbolAddress((void**)&W1lp, g_W1lp);
    cudaGetSymbolAddress((void**)&W2hp, g_W2hp); cudaGetSymbolAddress((void**)&W2lp, g_W2lp);
    cudaGetSymbolAddress((void**)&hPhA, g_hPhA); cudaGetSymbolAddress((void**)&hPlA, g_hPlA);
    cudaGetSymbolAddress((void**)&hPhB, g_hPhB); cudaGetSymbolAddress((void**)&hPlB, g_hPlB);
    __nv_bfloat16 *Winh, *Winl, *Hdh, *Hdl, *xh, *xl;
    cudaGetSymbolAddress((void**)&Winh, g_Winhi); cudaGetSymbolAddress((void**)&Winl, g_Winlo);
    cudaGetSymbolAddress((void**)&Hdh, g_Hdhi);   cudaGetSymbolAddress((void**)&Hdl, g_Hdlo);
    cudaGetSymbolAddress((void**)&xh, g_xhi);     cudaGetSymbolAddress((void**)&xl, g_xlo);

    cudaFuncSetAttribute(gemm_mma<0, 0>, cudaFuncAttributeMaxDynamicSharedMemorySize, SMEM_BYTES);
    cudaFuncSetAttribute(gemm_mma<2, 1>, cudaFuncAttributeMaxDynamicSharedMemorySize, SMEM_BYTES);
    cudaFuncSetAttribute(gemm_step, cudaFuncAttributeMaxDynamicSharedMemorySize, S_SMEM);

    // 0: prep (splits + packing + zeros + matvec_t + ticket reset)
    prep_kernel<<<592, 256>>>(W0, W1, W2, Winw, headw, x, u);
    // 1: sigma (matvec_s + reduce, ticket-synced)
    sigma_kernel<<<64, 256>>>(Winw, t, s, scal);
    // 2: x_proj (writes xpb[0..2] with per-layer bias folded)
    {
        dim3 grid(D_H / 64, BATCH / 64);
        gemm_mma<0, 0><<<grid, 128, SMEM_BYTES>>>(xh, xl, Winh, Winl, Winb,
                                                  nullptr, scal + 1, D_IN, D_H, D_H,
                                                  b0, b1, b2, xpb);
    }
    // 3..92: 30 steps x 3 layers
    const char* Whp[3] = {W0hp, W1hp, W2hp};
    const char* Wlp[3] = {W0lp, W1lp, W2lp};
    float *cur = hA, *nxt = hB;
    char *curh = hPhA, *curl = hPlA, *nxth = hPhB, *nxtl = hPlB;
    dim3 gstep(D_H / 64, BATCH / 64);
    for (int st = 0; st < STEPS; st++) {
        for (int l = 0; l < 3; l++) {
            gemm_step<<<gstep, 256, S_SMEM>>>(curh, curl, Whp[l], Wlp[l],
                                              xpb + (size_t)l * BATCH * D_H,
                                              cur, nxt, nxth, nxtl);
            float* tf = cur; cur = nxt; nxt = tf;
            char* th = curh; curh = nxth; nxth = th;
            char* tl = curl; curl = nxtl; nxtl = tl;
        }
    }
    // 93: head (A = packed final h)
    {
        dim3 grid((D_OUT + 63) / 64, BATCH / 64);
        gemm_mma<2, 1><<<grid, 128, SMEM_BYTES>>>(curh, curl, Hdh, Hdl, headb,
                                                  out, nullptr, D_H, D_OUT, D_OUT,
                                                  nullptr, nullptr, nullptr, nullptr);
    }
}